// round 13
// baseline (speedup 1.0000x reference)
#include <cuda_runtime.h>
#include <cuda_fp16.h>
#include <cuda_bf16.h>
#include <mma.h>
#include <cstdint>

using namespace nvcuda;

// ---------------- problem constants ----------------
#define NB 8            // batch
#define HW 384
#define CIN 3
#define PATCH 16
#define GRID 24         // 384/16
#define L 576           // GRID*GRID tokens
#define W 768           // width
#define DPT 4           // depth
#define NH 12           // heads
#define HD 64           // head dim
#define MLP 3072
#define M_ROWS (NB*L)   // 4608

// ---------------- scratch (device globals; no allocation allowed) ----------
__device__ float g_x[M_ROWS * W];     // residual stream
__device__ float g_y[M_ROWS * W];     // LN output / im2col buffer
__device__ float g_q[M_ROWS * W];
__device__ float g_k[M_ROWS * W];
__device__ float g_v[M_ROWS * W];
__device__ float g_o[M_ROWS * W];
__device__ float g_h[M_ROWS * MLP];   // MLP hidden
__device__ float g_rope[4][L][16];    // cosx,sinx,cosy,siny

// ---------------- helpers ----------------
__device__ __forceinline__ float gelu_tanh(float x) {
    const float k0 = 0.7978845608028654f;   // sqrt(2/pi)
    float x3 = x * x * x;
    return 0.5f * x * (1.0f + tanhf(k0 * (x + 0.044715f * x3)));
}

// store 4 floats as 4 fp16 (RN) at an 8B-aligned smem address
__device__ __forceinline__ void st_half4(__half* d, float4 t) {
    *(__half2*)(d)     = __floats2half2_rn(t.x, t.y);
    *(__half2*)(d + 2) = __floats2half2_rn(t.z, t.w);
}

// ---------------- im2col: image(NHWC) -> rows [NB*L, 768] -------------------
__global__ void im2col_kernel(const float* __restrict__ img, float* __restrict__ out) {
    int idx = blockIdx.x * blockDim.x + threadIdx.x;
    const int total = M_ROWS * W;
    if (idx >= total) return;
    int col = idx % W;
    int rest = idx / W;
    int p = rest % L;
    int n = rest / L;
    int c = col % CIN;
    int ij = col / CIN;
    int j = ij % PATCH;
    int i = ij / PATCH;
    int px = p % GRID, py = p / GRID;
    out[idx] = img[(((size_t)n * HW + (py * PATCH + i)) * HW + (px * PATCH + j)) * CIN + c];
}

// ---------------- RoPE cache ----------------
__global__ void rope_cache_kernel() {
    int idx = blockIdx.x * blockDim.x + threadIdx.x;
    if (idx >= L * 16) return;
    int l = idx / 16, f = idx % 16;
    int px = l % GRID, py = l / GRID;
    float u = (px + 0.5f) / (float)GRID;
    float v = (py + 0.5f) / (float)GRID;
    float fr = (float)f / (15.0f + 1e-9f);
    float inv = expf(-fr * 9.210340371976184f);  // 10000^-fr
    float ax = u * inv, ay = v * inv;
    g_rope[0][l][f] = cosf(ax);
    g_rope[1][l][f] = sinf(ax);
    g_rope[2][l][f] = cosf(ay);
    g_rope[3][l][f] = sinf(ay);
}

// ---------------- RoPE apply (in place on q or k) ----------------
__global__ void rope_apply_kernel(float* __restrict__ t) {
    int idx = blockIdx.x * blockDim.x + threadIdx.x;
    const int total = NB * L * NH * 32;   // 32 pairs per head
    if (idx >= total) return;
    int pair = idx & 31;
    int rest = idx >> 5;
    int h = rest % NH; rest /= NH;
    int l = rest % L;
    int n = rest / L;
    int f = pair & 15;
    float c, s;
    if (pair < 16) { c = g_rope[0][l][f]; s = g_rope[1][l][f]; }
    else           { c = g_rope[2][l][f]; s = g_rope[3][l][f]; }
    size_t base = ((((size_t)n * L + l) * NH + h) * HD) + pair * 2;
    float x = t[base], y = t[base + 1];
    t[base]     = x * c - y * s;
    t[base + 1] = x * s + y * c;
}

// ---------------- LayerNorm: warp per row, C = 768 fixed ----------------
__global__ void ln_warp(const float* __restrict__ x, const float* __restrict__ sc,
                        const float* __restrict__ bi, float* __restrict__ y) {
    int wid = threadIdx.x >> 5, lane = threadIdx.x & 31;
    int row = blockIdx.x * 8 + wid;
    const float4* xr = (const float4*)(x + (size_t)row * W);
    float4 v[6];
    float s1 = 0.f, s2 = 0.f;
    #pragma unroll
    for (int i = 0; i < 6; i++) {
        v[i] = xr[lane + 32 * i];
        s1 += v[i].x + v[i].y + v[i].z + v[i].w;
        s2 += v[i].x * v[i].x + v[i].y * v[i].y + v[i].z * v[i].z + v[i].w * v[i].w;
    }
    #pragma unroll
    for (int o = 16; o > 0; o >>= 1) {
        s1 += __shfl_xor_sync(0xffffffffu, s1, o);
        s2 += __shfl_xor_sync(0xffffffffu, s2, o);
    }
    float mean = s1 * (1.0f / W);
    float var  = s2 * (1.0f / W) - mean * mean;
    float rstd = rsqrtf(var + 1e-6f);
    float4* yr = (float4*)(y + (size_t)row * W);
    const float4* s4 = (const float4*)sc;
    const float4* b4 = (const float4*)bi;
    #pragma unroll
    for (int i = 0; i < 6; i++) {
        int idx = lane + 32 * i;
        float4 sv = s4[idx], bv = b4[idx], o;
        o.x = (v[i].x - mean) * rstd * sv.x + bv.x;
        o.y = (v[i].y - mean) * rstd * sv.y + bv.y;
        o.z = (v[i].z - mean) * rstd * sv.z + bv.z;
        o.w = (v[i].w - mean) * rstd * sv.w + bv.w;
        yr[idx] = o;
    }
}

// ---------------- tensor-core fp16 GEMM (fp32 accum), reg double-buffer -----
// C[M,N] = A[M,K] @ B[K,N] + bias[N]   (MODE 0)
//          gelu(...)                   (MODE 1)
//          ... + R[M,N]                (MODE 2)
#define GBM 128
#define GBN 128
#define GBK 32
#define LDA_S 40    // halves; 80B row stride (16B-multiple)
#define LDB_S 136   // halves; 272B row stride

template <int MODE>
__global__ __launch_bounds__(256) void gemm_tc(
        const float* __restrict__ A, const float* __restrict__ B,
        const float* __restrict__ bias, const float* __restrict__ R,
        float* __restrict__ C, int M, int N, int K) {
    __shared__ __align__(16) __half sA[GBM * LDA_S];   // 10240 B
    __shared__ __align__(16) __half sB[GBK * LDB_S];   //  8704 B

    int tid = threadIdx.x;           // 256
    int wid = tid >> 5, lane = tid & 31;
    int warp_m = wid >> 2;           // 0..1
    int warp_n = wid & 3;            // 0..3
    int row0 = blockIdx.y * GBM, col0 = blockIdx.x * GBN;

    wmma::fragment<wmma::accumulator, 16, 16, 16, float> acc[4][2];
    #pragma unroll
    for (int i = 0; i < 4; i++)
        #pragma unroll
        for (int j = 0; j < 2; j++)
            wmma::fill_fragment(acc[i][j], 0.0f);

    float4 pa[4], pb[4];
    #pragma unroll
    for (int i = 0; i < 4; i++) {
        int idx = tid + i * 256;
        pa[i] = *(const float4*)(A + (size_t)(row0 + (idx >> 3)) * K + ((idx & 7) * 4));
        pb[i] = *(const float4*)(B + (size_t)(idx >> 5) * N + col0 + ((idx & 31) * 4));
    }
    #pragma unroll
    for (int i = 0; i < 4; i++) {
        int idx = tid + i * 256;
        st_half4(&sA[(idx >> 3) * LDA_S + (idx & 7) * 4], pa[i]);
        st_half4(&sB[(idx >> 5) * LDB_S + (idx & 31) * 4], pb[i]);
    }
    __syncthreads();

    int KT = K / GBK;
    for (int kt = 0; kt < KT; kt++) {
        if (kt + 1 < KT) {
            int k0 = (kt + 1) * GBK;
            #pragma unroll
            for (int i = 0; i < 4; i++) {
                int idx = tid + i * 256;
                pa[i] = *(const float4*)(A + (size_t)(row0 + (idx >> 3)) * K + k0 + ((idx & 7) * 4));
                pb[i] = *(const float4*)(B + (size_t)(k0 + (idx >> 5)) * N + col0 + ((idx & 31) * 4));
            }
        }
        #pragma unroll
        for (int ks = 0; ks < 2; ks++) {
            wmma::fragment<wmma::matrix_a, 16, 16, 16, __half, wmma::row_major> af[4];
            wmma::fragment<wmma::matrix_b, 16, 16, 16, __half, wmma::row_major> bf[2];
            #pragma unroll
            for (int i = 0; i < 4; i++)
                wmma::load_matrix_sync(af[i], &sA[(warp_m * 64 + i * 16) * LDA_S + ks * 16], LDA_S);
            #pragma unroll
            for (int j = 0; j < 2; j++)
                wmma::load_matrix_sync(bf[j], &sB[(ks * 16) * LDB_S + warp_n * 32 + j * 16], LDB_S);
            #pragma unroll
            for (int i = 0; i < 4; i++)
                #pragma unroll
                for (int j = 0; j < 2; j++)
                    wmma::mma_sync(acc[i][j], af[i], bf[j], acc[i][j]);
        }
        __syncthreads();
        if (kt + 1 < KT) {
            #pragma unroll
            for (int i = 0; i < 4; i++) {
                int idx = tid + i * 256;
                st_half4(&sA[(idx >> 3) * LDA_S + (idx & 7) * 4], pa[i]);
                st_half4(&sB[(idx >> 5) * LDB_S + (idx & 31) * 4], pb[i]);
            }
            __syncthreads();
        }
    }

    // epilogue: stage each 16x16 frag through per-warp smem patch (alias sA)
    float* stage = reinterpret_cast<float*>(sA) + wid * 272;
    int r = lane >> 1, c0 = (lane & 1) * 8;
    #pragma unroll
    for (int i = 0; i < 4; i++) {
        #pragma unroll
        for (int j = 0; j < 2; j++) {
            __syncwarp();
            wmma::store_matrix_sync(stage, acc[i][j], 16, wmma::mem_row_major);
            __syncwarp();
            int m = row0 + warp_m * 64 + i * 16 + r;
            int n = col0 + warp_n * 32 + j * 16 + c0;
            float bb[8];
            *(float4*)(bb)     = *(const float4*)(bias + n);
            *(float4*)(bb + 4) = *(const float4*)(bias + n + 4);
            float out[8];
            #pragma unroll
            for (int t = 0; t < 8; t++) out[t] = stage[r * 16 + c0 + t] + bb[t];
            if (MODE == 1) {
                #pragma unroll
                for (int t = 0; t < 8; t++) out[t] = gelu_tanh(out[t]);
            }
            if (MODE == 2) {
                float rr[8];
                *(float4*)(rr)     = *(const float4*)(R + (size_t)m * N + n);
                *(float4*)(rr + 4) = *(const float4*)(R + (size_t)m * N + n + 4);
                #pragma unroll
                for (int t = 0; t < 8; t++) out[t] += rr[t];
            }
            *(float4*)(C + (size_t)m * N + n)     = *(float4*)(out);
            *(float4*)(C + (size_t)m * N + n + 4) = *(float4*)(out + 4);
        }
    }
}

// ---------------- fused attention: QK^T + softmax + P@V ---------------------
// One CTA per (64-query tile, n*NH+h). All 576 key scores live in smem.
//   sS  : 64 x 576 fp32 scores (row stride FA_LDS=584, ≡8 mod 32 banks)
//   probs packed fp16 in-place (half view, row stride 2*FA_LDS)
//   sQ  : 64 x 64 fp16 Q tile   (stride LDT)
//   sKV : 64 x 64 fp16 K/V tile (stride LDT, reused)
#define LDT 72        // halves; 144B row stride
#define FA_LDS 584    // floats per score row (584 % 32 == 8)
#define FA_SMEM (64 * FA_LDS * 4 + 2 * 64 * LDT * 2)   // 149504 + 18432 = 167936

__global__ __launch_bounds__(128) void attn_fused(
        const float* __restrict__ q, const float* __restrict__ k,
        const float* __restrict__ v, float* __restrict__ o) {
    extern __shared__ __align__(16) unsigned char fsm[];
    float*  sS  = reinterpret_cast<float*>(fsm);
    __half* sSh = reinterpret_cast<__half*>(fsm);           // half view of sS
    __half* sQ  = reinterpret_cast<__half*>(fsm + 64 * FA_LDS * 4);
    __half* sKV = sQ + 64 * LDT;

    int mt = blockIdx.x;          // query tile 0..8
    int nh = blockIdx.y;          // n*NH + h
    int n = nh / NH, h = nh % NH;
    const float* qb = q + ((size_t)n * L * NH + h) * HD;    // row stride 768
    const float* kb = k + ((size_t)n * L * NH + h) * HD;
    const float* vb = v + ((size_t)n * L * NH + h) * HD;
    float* ob = o + ((size_t)n * L * NH + h) * HD;

    int tid = threadIdx.x;        // 128
    int wid = tid >> 5, lane = tid & 31;
    int wm = wid >> 1, wn = wid & 1;    // 2x2 warp layout over 64x64 tiles

    // ---- load Q tile (64 rows x 64 dims) ----
    #pragma unroll
    for (int i = 0; i < 8; i++) {
        int idx = tid + i * 128;
        int row = idx >> 4, c4 = (idx & 15) * 4;
        float4 tq = *(const float4*)(qb + (size_t)(mt * 64 + row) * (NH * HD) + c4);
        st_half4(&sQ[row * LDT + c4], tq);
    }

    // ---- phase 1: S = Q K^T for all 9 key tiles, into sS ----
    for (int kt = 0; kt < L / 64; kt++) {
        __syncthreads();   // protect sKV reuse (and Q store on first iter)
        #pragma unroll
        for (int i = 0; i < 8; i++) {
            int idx = tid + i * 128;
            int row = idx >> 4, c4 = (idx & 15) * 4;
            float4 tk = *(const float4*)(kb + (size_t)(kt * 64 + row) * (NH * HD) + c4);
            st_half4(&sKV[row * LDT + c4], tk);
        }
        __syncthreads();
        wmma::fragment<wmma::accumulator, 16, 16, 16, float> acc[2][2];
        #pragma unroll
        for (int i = 0; i < 2; i++)
            #pragma unroll
            for (int j = 0; j < 2; j++) wmma::fill_fragment(acc[i][j], 0.0f);
        #pragma unroll
        for (int k0 = 0; k0 < HD; k0 += 16) {
            wmma::fragment<wmma::matrix_a, 16, 16, 16, __half, wmma::row_major> af[2];
            wmma::fragment<wmma::matrix_b, 16, 16, 16, __half, wmma::col_major> bf[2];
            #pragma unroll
            for (int i = 0; i < 2; i++)
                wmma::load_matrix_sync(af[i], &sQ[(wm * 32 + i * 16) * LDT + k0], LDT);
            #pragma unroll
            for (int j = 0; j < 2; j++)
                wmma::load_matrix_sync(bf[j], &sKV[(wn * 32 + j * 16) * LDT + k0], LDT);
            #pragma unroll
            for (int i = 0; i < 2; i++)
                #pragma unroll
                for (int j = 0; j < 2; j++)
                    wmma::mma_sync(acc[i][j], af[i], bf[j], acc[i][j]);
        }
        #pragma unroll
        for (int i = 0; i < 2; i++)
            #pragma unroll
            for (int j = 0; j < 2; j++)
                wmma::store_matrix_sync(&sS[(wm * 32 + i * 16) * FA_LDS + kt * 64 + wn * 32 + j * 16],
                                        acc[i][j], FA_LDS, wmma::mem_row_major);
    }
    __syncthreads();   // all S tiles written

    // ---- phase 2: softmax per row (warp w owns rows 16w..16w+15) ----
    // probs = exp(0.125*(s - max)) / sum, packed fp16 in-place.
    for (int rr = 0; rr < 16; rr++) {
        int row = wid * 16 + rr;
        float* rowp = sS + (size_t)row * FA_LDS;
        float r[18];
        float m = -1e30f;
        #pragma unroll
        for (int i = 0; i < 18; i++) { r[i] = rowp[lane + 32 * i]; m = fmaxf(m, r[i]); }
        #pragma unroll
        for (int off = 16; off > 0; off >>= 1) m = fmaxf(m, __shfl_xor_sync(0xffffffffu, m, off));
        float s = 0.f;
        #pragma unroll
        for (int i = 0; i < 18; i++) { r[i] = __expf(0.125f * (r[i] - m)); s += r[i]; }
        #pragma unroll
        for (int off = 16; off > 0; off >>= 1) s += __shfl_xor_sync(0xffffffffu, s, off);
        float inv = 1.0f / s;
        __syncwarp();   // all lanes done reading fp32 row before fp16 overwrite
        __half* rowh = sSh + (size_t)row * (2 * FA_LDS);
        #pragma unroll
        for (int i = 0; i < 18; i++) rowh[lane + 32 * i] = __float2half_rn(r[i] * inv);
    }
    __syncthreads();   // probs visible to all warps (cross-warp row reads in P@V)

    // ---- phase 3: O = P V, accumulate over 9 value tiles ----
    wmma::fragment<wmma::accumulator, 16, 16, 16, float> oacc[2][2];
    #pragma unroll
    for (int i = 0; i < 2; i++)
        #pragma unroll
        for (int j = 0; j < 2; j++) wmma::fill_fragment(oacc[i][j], 0.0f);

    for (int kt = 0; kt < L / 64; kt++) {
        #pragma unroll
        for (int i = 0; i < 8; i++) {
            int idx = tid + i * 128;
            int row = idx >> 4, c4 = (idx & 15) * 4;
            float4 tv = *(const float4*)(vb + (size_t)(kt * 64 + row) * (NH * HD) + c4);
            st_half4(&sKV[row * LDT + c4], tv);
        }
        __syncthreads();
        #pragma unroll
        for (int k0 = 0; k0 < 64; k0 += 16) {
            wmma::fragment<wmma::matrix_a, 16, 16, 16, __half, wmma::row_major> af[2];
            wmma::fragment<wmma::matrix_b, 16, 16, 16, __half, wmma::row_major> bf[2];
            #pragma unroll
            for (int i = 0; i < 2; i++)
                wmma::load_matrix_sync(af[i],
                    &sSh[(size_t)(wm * 32 + i * 16) * (2 * FA_LDS) + kt * 64 + k0], 2 * FA_LDS);
            #pragma unroll
            for (int j = 0; j < 2; j++)
                wmma::load_matrix_sync(bf[j], &sKV[k0 * LDT + wn * 32 + j * 16], LDT);
            #pragma unroll
            for (int i = 0; i < 2; i++)
                #pragma unroll
                for (int j = 0; j < 2; j++)
                    wmma::mma_sync(oacc[i][j], af[i], bf[j], oacc[i][j]);
        }
        __syncthreads();   // V tile consumed before next overwrite
    }

    int row0 = mt * 64 + wm * 32;
    int col0 = wn * 32;
    #pragma unroll
    for (int i = 0; i < 2; i++)
        #pragma unroll
        for (int j = 0; j < 2; j++)
            wmma::store_matrix_sync(ob + (size_t)(row0 + i * 16) * (NH * HD) + col0 + j * 16,
                                    oacc[i][j], NH * HD, wmma::mem_row_major);
}

// ---------------- final mean over tokens ----------------
__global__ void mean_kernel(const float* __restrict__ y, float* __restrict__ out) {
    int n = blockIdx.x;
    int c = threadIdx.x;   // 768
    float s = 0.f;
    for (int l = 0; l < L; l++) s += y[((size_t)n * L + l) * W + c];
    out[n * W + c] = s * (1.0f / (float)L);
}

// ---------------- host orchestration ----------------
extern "C" void kernel_launch(void* const* d_in, const int* in_sizes, int n_in,
                              void* d_out, int out_size) {
    const float* image   = (const float*)d_in[0];
    const float* ckern   = (const float*)d_in[1];
    const float* cbias   = (const float*)d_in[2];
    const float* ln1s    = (const float*)d_in[3];
    const float* ln1b    = (const float*)d_in[4];
    const float* wq      = (const float*)d_in[5];
    const float* bq      = (const float*)d_in[6];
    const float* wk      = (const float*)d_in[7];
    const float* bk      = (const float*)d_in[8];
    const float* wv      = (const float*)d_in[9];
    const float* bv      = (const float*)d_in[10];
    const float* wo      = (const float*)d_in[11];
    const float* bo      = (const float*)d_in[12];
    const float* ln2s    = (const float*)d_in[13];
    const float* ln2b    = (const float*)d_in[14];
    const float* w1      = (const float*)d_in[15];
    const float* b1      = (const float*)d_in[16];
    const float* w2      = (const float*)d_in[17];
    const float* b2      = (const float*)d_in[18];
    const float* lnfs    = (const float*)d_in[19];
    const float* lnfb    = (const float*)d_in[20];
    float* out = (float*)d_out;

    float *x, *y, *q, *k, *v, *o, *hbuf;
    cudaGetSymbolAddress((void**)&x, g_x);
    cudaGetSymbolAddress((void**)&y, g_y);
    cudaGetSymbolAddress((void**)&q, g_q);
    cudaGetSymbolAddress((void**)&k, g_k);
    cudaGetSymbolAddress((void**)&v, g_v);
    cudaGetSymbolAddress((void**)&o, g_o);
    cudaGetSymbolAddress((void**)&hbuf, g_h);

    cudaFuncSetAttribute(attn_fused, cudaFuncAttributeMaxDynamicSharedMemorySize, FA_SMEM);

    const size_t WW = (size_t)W * W;
    const size_t WM = (size_t)W * MLP;

    // patch embed: im2col + GEMM
    {
        int total = M_ROWS * W;
        im2col_kernel<<<(total + 255) / 256, 256>>>(image, y);
        dim3 gg(W / GBN, M_ROWS / GBM);
        gemm_tc<0><<<gg, 256>>>(y, ckern, cbias, nullptr, x, M_ROWS, W, W);
    }
    rope_cache_kernel<<<(L * 16 + 255) / 256, 256>>>();

    dim3 gw(W / GBN, M_ROWS / GBM);       // 768-wide GEMMs: (6, 36)
    dim3 gm(MLP / GBN, M_ROWS / GBM);     // 3072-wide GEMM:  (24, 36)
    int rope_total = NB * L * NH * 32;
    dim3 gat(L / 64, NB * NH);            // fused attention: (9, 96)

    for (int l = 0; l < DPT; l++) {
        ln_warp<<<M_ROWS / 8, 256>>>(x, ln1s + l * W, ln1b + l * W, y);
        gemm_tc<0><<<gw, 256>>>(y, wq + l * WW, bq + l * W, nullptr, q, M_ROWS, W, W);
        gemm_tc<0><<<gw, 256>>>(y, wk + l * WW, bk + l * W, nullptr, k, M_ROWS, W, W);
        gemm_tc<0><<<gw, 256>>>(y, wv + l * WW, bv + l * W, nullptr, v, M_ROWS, W, W);
        rope_apply_kernel<<<(rope_total + 255) / 256, 256>>>(q);
        rope_apply_kernel<<<(rope_total + 255) / 256, 256>>>(k);
        attn_fused<<<gat, 128, FA_SMEM>>>(q, k, v, o);
        // x = x + (o @ wo + bo)
        gemm_tc<2><<<gw, 256>>>(o, wo + l * WW, bo + l * W, x, x, M_ROWS, W, W);
        ln_warp<<<M_ROWS / 8, 256>>>(x, ln2s + l * W, ln2b + l * W, y);
        gemm_tc<1><<<gm, 256>>>(y, w1 + l * WM, b1 + l * MLP, nullptr, hbuf, M_ROWS, MLP, W);
        gemm_tc<2><<<gw, 256>>>(hbuf, w2 + l * WM, b2 + l * W, x, x, M_ROWS, W, MLP);
    }

    ln_warp<<<M_ROWS / 8, 256>>>(x, lnfs, lnfb, y);
    mean_kernel<<<NB, W>>>(y, out);
}

// round 14
// speedup vs baseline: 1.0368x; 1.0368x over previous
#include <cuda_runtime.h>
#include <cuda_fp16.h>
#include <cuda_bf16.h>
#include <mma.h>
#include <cstdint>

using namespace nvcuda;

// ---------------- problem constants ----------------
#define NB 8            // batch
#define HW 384
#define CIN 3
#define PATCH 16
#define GRID 24         // 384/16
#define L 576           // GRID*GRID tokens
#define W 768           // width
#define DPT 4           // depth
#define NH 12           // heads
#define HD 64           // head dim
#define MLP 3072
#define M_ROWS (NB*L)   // 4608

// ---------------- scratch (device globals; no allocation allowed) ----------
__device__ float g_x[M_ROWS * W];     // residual stream
__device__ float g_y[M_ROWS * W];     // LN output / im2col buffer
__device__ float g_q[M_ROWS * W];
__device__ float g_k[M_ROWS * W];
__device__ float g_v[M_ROWS * W];
__device__ float g_o[M_ROWS * W];
__device__ float g_h[M_ROWS * MLP];   // MLP hidden
__device__ float g_rope[4][L][16];    // cosx,sinx,cosy,siny

// ---------------- helpers ----------------
__device__ __forceinline__ float gelu_tanh(float x) {
    const float k0 = 0.7978845608028654f;   // sqrt(2/pi)
    float x3 = x * x * x;
    return 0.5f * x * (1.0f + tanhf(k0 * (x + 0.044715f * x3)));
}

// store 4 floats as 4 fp16 (RN) at an 8B-aligned smem address
__device__ __forceinline__ void st_half4(__half* d, float4 t) {
    *(__half2*)(d)     = __floats2half2_rn(t.x, t.y);
    *(__half2*)(d + 2) = __floats2half2_rn(t.z, t.w);
}

// ---------------- im2col: image(NHWC) -> rows [NB*L, 768] -------------------
__global__ void im2col_kernel(const float* __restrict__ img, float* __restrict__ out) {
    int idx = blockIdx.x * blockDim.x + threadIdx.x;
    const int total = M_ROWS * W;
    if (idx >= total) return;
    int col = idx % W;
    int rest = idx / W;
    int p = rest % L;
    int n = rest / L;
    int c = col % CIN;
    int ij = col / CIN;
    int j = ij % PATCH;
    int i = ij / PATCH;
    int px = p % GRID, py = p / GRID;
    out[idx] = img[(((size_t)n * HW + (py * PATCH + i)) * HW + (px * PATCH + j)) * CIN + c];
}

// ---------------- RoPE cache ----------------
__global__ void rope_cache_kernel() {
    int idx = blockIdx.x * blockDim.x + threadIdx.x;
    if (idx >= L * 16) return;
    int l = idx / 16, f = idx % 16;
    int px = l % GRID, py = l / GRID;
    float u = (px + 0.5f) / (float)GRID;
    float v = (py + 0.5f) / (float)GRID;
    float fr = (float)f / (15.0f + 1e-9f);
    float inv = expf(-fr * 9.210340371976184f);  // 10000^-fr
    float ax = u * inv, ay = v * inv;
    g_rope[0][l][f] = cosf(ax);
    g_rope[1][l][f] = sinf(ax);
    g_rope[2][l][f] = cosf(ay);
    g_rope[3][l][f] = sinf(ay);
}

// ---------------- LayerNorm: warp per row, C = 768 fixed ----------------
__global__ void ln_warp(const float* __restrict__ x, const float* __restrict__ sc,
                        const float* __restrict__ bi, float* __restrict__ y) {
    int wid = threadIdx.x >> 5, lane = threadIdx.x & 31;
    int row = blockIdx.x * 8 + wid;
    const float4* xr = (const float4*)(x + (size_t)row * W);
    float4 v[6];
    float s1 = 0.f, s2 = 0.f;
    #pragma unroll
    for (int i = 0; i < 6; i++) {
        v[i] = xr[lane + 32 * i];
        s1 += v[i].x + v[i].y + v[i].z + v[i].w;
        s2 += v[i].x * v[i].x + v[i].y * v[i].y + v[i].z * v[i].z + v[i].w * v[i].w;
    }
    #pragma unroll
    for (int o = 16; o > 0; o >>= 1) {
        s1 += __shfl_xor_sync(0xffffffffu, s1, o);
        s2 += __shfl_xor_sync(0xffffffffu, s2, o);
    }
    float mean = s1 * (1.0f / W);
    float var  = s2 * (1.0f / W) - mean * mean;
    float rstd = rsqrtf(var + 1e-6f);
    float4* yr = (float4*)(y + (size_t)row * W);
    const float4* s4 = (const float4*)sc;
    const float4* b4 = (const float4*)bi;
    #pragma unroll
    for (int i = 0; i < 6; i++) {
        int idx = lane + 32 * i;
        float4 sv = s4[idx], bv = b4[idx], o;
        o.x = (v[i].x - mean) * rstd * sv.x + bv.x;
        o.y = (v[i].y - mean) * rstd * sv.y + bv.y;
        o.z = (v[i].z - mean) * rstd * sv.z + bv.z;
        o.w = (v[i].w - mean) * rstd * sv.w + bv.w;
        yr[idx] = o;
    }
}

// ---------------- shared GEMM tile params ----------------
#define GBM 128
#define GBN 128
#define GBK 32
#define LDA_S 40    // halves; 80B row stride (16B-multiple)
#define LDB_S 136   // halves; 272B row stride

// mainloop body shared by both GEMM kernels (reg prefetch + fp16 smem tiles)
#define GEMM_MAINLOOP(Aptr, Bptr)                                                        \
    float4 pa[4], pb[4];                                                                 \
    _Pragma("unroll")                                                                    \
    for (int i = 0; i < 4; i++) {                                                        \
        int idx = tid + i * 256;                                                         \
        pa[i] = *(const float4*)(Aptr + (size_t)(row0 + (idx >> 3)) * K + ((idx & 7) * 4)); \
        pb[i] = *(const float4*)(Bptr + (size_t)(idx >> 5) * N + col0 + ((idx & 31) * 4));  \
    }                                                                                    \
    _Pragma("unroll")                                                                    \
    for (int i = 0; i < 4; i++) {                                                        \
        int idx = tid + i * 256;                                                         \
        st_half4(&sA[(idx >> 3) * LDA_S + (idx & 7) * 4], pa[i]);                        \
        st_half4(&sB[(idx >> 5) * LDB_S + (idx & 31) * 4], pb[i]);                       \
    }                                                                                    \
    __syncthreads();                                                                     \
    int KT = K / GBK;                                                                    \
    for (int kt = 0; kt < KT; kt++) {                                                    \
        if (kt + 1 < KT) {                                                               \
            int k0 = (kt + 1) * GBK;                                                     \
            _Pragma("unroll")                                                            \
            for (int i = 0; i < 4; i++) {                                                \
                int idx = tid + i * 256;                                                 \
                pa[i] = *(const float4*)(Aptr + (size_t)(row0 + (idx >> 3)) * K + k0 + ((idx & 7) * 4)); \
                pb[i] = *(const float4*)(Bptr + (size_t)(k0 + (idx >> 5)) * N + col0 + ((idx & 31) * 4)); \
            }                                                                            \
        }                                                                                \
        _Pragma("unroll")                                                                \
        for (int ks = 0; ks < 2; ks++) {                                                 \
            wmma::fragment<wmma::matrix_a, 16, 16, 16, __half, wmma::row_major> af[4];   \
            wmma::fragment<wmma::matrix_b, 16, 16, 16, __half, wmma::row_major> bf[2];   \
            _Pragma("unroll")                                                            \
            for (int i = 0; i < 4; i++)                                                  \
                wmma::load_matrix_sync(af[i], &sA[(warp_m * 64 + i * 16) * LDA_S + ks * 16], LDA_S); \
            _Pragma("unroll")                                                            \
            for (int j = 0; j < 2; j++)                                                  \
                wmma::load_matrix_sync(bf[j], &sB[(ks * 16) * LDB_S + warp_n * 32 + j * 16], LDB_S); \
            _Pragma("unroll")                                                            \
            for (int i = 0; i < 4; i++)                                                  \
                _Pragma("unroll")                                                        \
                for (int j = 0; j < 2; j++)                                              \
                    wmma::mma_sync(acc[i][j], af[i], bf[j], acc[i][j]);                  \
        }                                                                                \
        __syncthreads();                                                                 \
        if (kt + 1 < KT) {                                                               \
            _Pragma("unroll")                                                            \
            for (int i = 0; i < 4; i++) {                                                \
                int idx = tid + i * 256;                                                 \
                st_half4(&sA[(idx >> 3) * LDA_S + (idx & 7) * 4], pa[i]);                \
                st_half4(&sB[(idx >> 5) * LDB_S + (idx & 31) * 4], pb[i]);               \
            }                                                                            \
            __syncthreads();                                                             \
        }                                                                                \
    }

// ---------------- generic fp16 GEMM with fused epilogue ---------------------
// C[M,N] = A[M,K] @ B[K,N] + bias[N]   (MODE 0)
//          gelu(...)                   (MODE 1)
//          ... + R[M,N]                (MODE 2)
template <int MODE>
__global__ __launch_bounds__(256, 2) void gemm_tc(
        const float* __restrict__ A, const float* __restrict__ B,
        const float* __restrict__ bias, const float* __restrict__ R,
        float* __restrict__ C, int M, int N, int K) {
    __shared__ __align__(16) __half sA[GBM * LDA_S];   // 10240 B
    __shared__ __align__(16) __half sB[GBK * LDB_S];   //  8704 B

    int tid = threadIdx.x;           // 256
    int wid = tid >> 5, lane = tid & 31;
    int warp_m = wid >> 2;           // 0..1
    int warp_n = wid & 3;            // 0..3
    int row0 = blockIdx.y * GBM, col0 = blockIdx.x * GBN;

    wmma::fragment<wmma::accumulator, 16, 16, 16, float> acc[4][2];
    #pragma unroll
    for (int i = 0; i < 4; i++)
        #pragma unroll
        for (int j = 0; j < 2; j++)
            wmma::fill_fragment(acc[i][j], 0.0f);

    GEMM_MAINLOOP(A, B)

    // epilogue: stage each 16x16 frag through per-warp smem patch (alias sA)
    float* stage = reinterpret_cast<float*>(sA) + wid * 272;
    int r = lane >> 1, c0 = (lane & 1) * 8;
    #pragma unroll
    for (int i = 0; i < 4; i++) {
        #pragma unroll
        for (int j = 0; j < 2; j++) {
            __syncwarp();
            wmma::store_matrix_sync(stage, acc[i][j], 16, wmma::mem_row_major);
            __syncwarp();
            int m = row0 + warp_m * 64 + i * 16 + r;
            int n = col0 + warp_n * 32 + j * 16 + c0;
            float bb[8];
            *(float4*)(bb)     = *(const float4*)(bias + n);
            *(float4*)(bb + 4) = *(const float4*)(bias + n + 4);
            float out[8];
            #pragma unroll
            for (int t = 0; t < 8; t++) out[t] = stage[r * 16 + c0 + t] + bb[t];
            if (MODE == 1) {
                #pragma unroll
                for (int t = 0; t < 8; t++) out[t] = gelu_tanh(out[t]);
            }
            if (MODE == 2) {
                float rr[8];
                *(float4*)(rr)     = *(const float4*)(R + (size_t)m * N + n);
                *(float4*)(rr + 4) = *(const float4*)(R + (size_t)m * N + n + 4);
                #pragma unroll
                for (int t = 0; t < 8; t++) out[t] += rr[t];
            }
            *(float4*)(C + (size_t)m * N + n)     = *(float4*)(out);
            *(float4*)(C + (size_t)m * N + n + 4) = *(float4*)(out + 4);
        }
    }
}

// ---------------- fused QKV GEMM: z selects {q,k,v}; rope fused for q,k -----
__global__ __launch_bounds__(256, 2) void gemm_qkv(
        const float* __restrict__ A,
        const float* __restrict__ Bq, const float* __restrict__ Bk, const float* __restrict__ Bv,
        const float* __restrict__ bq, const float* __restrict__ bk, const float* __restrict__ bv,
        float* __restrict__ Cq, float* __restrict__ Ck, float* __restrict__ Cv,
        int M, int N, int K) {
    __shared__ __align__(16) __half sA[GBM * LDA_S];
    __shared__ __align__(16) __half sB[GBK * LDB_S];

    int tid = threadIdx.x;
    int wid = tid >> 5, lane = tid & 31;
    int warp_m = wid >> 2;
    int warp_n = wid & 3;
    int row0 = blockIdx.y * GBM, col0 = blockIdx.x * GBN;
    int z = blockIdx.z;
    const float* B    = (z == 0) ? Bq : (z == 1) ? Bk : Bv;
    const float* bias = (z == 0) ? bq : (z == 1) ? bk : bv;
    float* C          = (z == 0) ? Cq : (z == 1) ? Ck : Cv;
    bool do_rope = (z < 2);

    wmma::fragment<wmma::accumulator, 16, 16, 16, float> acc[4][2];
    #pragma unroll
    for (int i = 0; i < 4; i++)
        #pragma unroll
        for (int j = 0; j < 2; j++)
            wmma::fill_fragment(acc[i][j], 0.0f);

    GEMM_MAINLOOP(A, B)

    // epilogue with fused RoPE: each thread owns 8 consecutive cols = 4 pairs
    float* stage = reinterpret_cast<float*>(sA) + wid * 272;
    int r = lane >> 1, c0 = (lane & 1) * 8;
    #pragma unroll
    for (int i = 0; i < 4; i++) {
        #pragma unroll
        for (int j = 0; j < 2; j++) {
            __syncwarp();
            wmma::store_matrix_sync(stage, acc[i][j], 16, wmma::mem_row_major);
            __syncwarp();
            int m = row0 + warp_m * 64 + i * 16 + r;
            int n = col0 + warp_n * 32 + j * 16 + c0;
            float bb[8];
            *(float4*)(bb)     = *(const float4*)(bias + n);
            *(float4*)(bb + 4) = *(const float4*)(bias + n + 4);
            float out[8];
            #pragma unroll
            for (int t = 0; t < 8; t++) out[t] = stage[r * 16 + c0 + t] + bb[t];
            if (do_rope) {
                int l = m % L;           // token index
                int d0 = n & 63;         // dim within head (multiple of 8)
                #pragma unroll
                for (int t = 0; t < 8; t += 2) {
                    int pair = (d0 + t) >> 1;      // 0..31
                    int f = pair & 15;
                    int hi = pair >> 4;            // 0: x-rope, 1: y-rope
                    float cc = g_rope[hi ? 2 : 0][l][f];
                    float ss = g_rope[hi ? 3 : 1][l][f];
                    float xv = out[t], yv = out[t + 1];
                    out[t]     = xv * cc - yv * ss;
                    out[t + 1] = xv * ss + yv * cc;
                }
            }
            *(float4*)(C + (size_t)m * N + n)     = *(float4*)(out);
            *(float4*)(C + (size_t)m * N + n + 4) = *(float4*)(out + 4);
        }
    }
}

// ---------------- fused attention: QK^T + softmax + P@V ---------------------
// One CTA per (64-query tile, n*NH+h). All 576 key scores live in smem.
#define LDT 72        // halves; 144B row stride
#define FA_LDS 584    // floats per score row (584 % 32 == 8)
#define FA_SMEM (64 * FA_LDS * 4 + 2 * 64 * LDT * 2)   // 167936

__global__ __launch_bounds__(128) void attn_fused(
        const float* __restrict__ q, const float* __restrict__ k,
        const float* __restrict__ v, float* __restrict__ o) {
    extern __shared__ __align__(16) unsigned char fsm[];
    float*  sS  = reinterpret_cast<float*>(fsm);
    __half* sSh = reinterpret_cast<__half*>(fsm);           // half view of sS
    __half* sQ  = reinterpret_cast<__half*>(fsm + 64 * FA_LDS * 4);
    __half* sKV = sQ + 64 * LDT;

    int mt = blockIdx.x;          // query tile 0..8
    int nh = blockIdx.y;          // n*NH + h
    int n = nh / NH, h = nh % NH;
    const float* qb = q + ((size_t)n * L * NH + h) * HD;    // row stride 768
    const float* kb = k + ((size_t)n * L * NH + h) * HD;
    const float* vb = v + ((size_t)n * L * NH + h) * HD;
    float* ob = o + ((size_t)n * L * NH + h) * HD;

    int tid = threadIdx.x;        // 128
    int wid = tid >> 5, lane = tid & 31;
    int wm = wid >> 1, wn = wid & 1;    // 2x2 warp layout over 64x64 tiles

    // ---- load Q tile ----
    #pragma unroll
    for (int i = 0; i < 8; i++) {
        int idx = tid + i * 128;
        int row = idx >> 4, c4 = (idx & 15) * 4;
        float4 tq = *(const float4*)(qb + (size_t)(mt * 64 + row) * (NH * HD) + c4);
        st_half4(&sQ[row * LDT + c4], tq);
    }

    // ---- phase 1: S = Q K^T ----
    for (int kt = 0; kt < L / 64; kt++) {
        __syncthreads();
        #pragma unroll
        for (int i = 0; i < 8; i++) {
            int idx = tid + i * 128;
            int row = idx >> 4, c4 = (idx & 15) * 4;
            float4 tk = *(const float4*)(kb + (size_t)(kt * 64 + row) * (NH * HD) + c4);
            st_half4(&sKV[row * LDT + c4], tk);
        }
        __syncthreads();
        wmma::fragment<wmma::accumulator, 16, 16, 16, float> acc[2][2];
        #pragma unroll
        for (int i = 0; i < 2; i++)
            #pragma unroll
            for (int j = 0; j < 2; j++) wmma::fill_fragment(acc[i][j], 0.0f);
        #pragma unroll
        for (int k0 = 0; k0 < HD; k0 += 16) {
            wmma::fragment<wmma::matrix_a, 16, 16, 16, __half, wmma::row_major> af[2];
            wmma::fragment<wmma::matrix_b, 16, 16, 16, __half, wmma::col_major> bf[2];
            #pragma unroll
            for (int i = 0; i < 2; i++)
                wmma::load_matrix_sync(af[i], &sQ[(wm * 32 + i * 16) * LDT + k0], LDT);
            #pragma unroll
            for (int j = 0; j < 2; j++)
                wmma::load_matrix_sync(bf[j], &sKV[(wn * 32 + j * 16) * LDT + k0], LDT);
            #pragma unroll
            for (int i = 0; i < 2; i++)
                #pragma unroll
                for (int j = 0; j < 2; j++)
                    wmma::mma_sync(acc[i][j], af[i], bf[j], acc[i][j]);
        }
        #pragma unroll
        for (int i = 0; i < 2; i++)
            #pragma unroll
            for (int j = 0; j < 2; j++)
                wmma::store_matrix_sync(&sS[(wm * 32 + i * 16) * FA_LDS + kt * 64 + wn * 32 + j * 16],
                                        acc[i][j], FA_LDS, wmma::mem_row_major);
    }
    __syncthreads();

    // ---- phase 2: softmax per row ----
    for (int rr = 0; rr < 16; rr++) {
        int row = wid * 16 + rr;
        float* rowp = sS + (size_t)row * FA_LDS;
        float r[18];
        float m = -1e30f;
        #pragma unroll
        for (int i = 0; i < 18; i++) { r[i] = rowp[lane + 32 * i]; m = fmaxf(m, r[i]); }
        #pragma unroll
        for (int off = 16; off > 0; off >>= 1) m = fmaxf(m, __shfl_xor_sync(0xffffffffu, m, off));
        float s = 0.f;
        #pragma unroll
        for (int i = 0; i < 18; i++) { r[i] = __expf(0.125f * (r[i] - m)); s += r[i]; }
        #pragma unroll
        for (int off = 16; off > 0; off >>= 1) s += __shfl_xor_sync(0xffffffffu, s, off);
        float inv = 1.0f / s;
        __syncwarp();
        __half* rowh = sSh + (size_t)row * (2 * FA_LDS);
        #pragma unroll
        for (int i = 0; i < 18; i++) rowh[lane + 32 * i] = __float2half_rn(r[i] * inv);
    }
    __syncthreads();

    // ---- phase 3: O = P V ----
    wmma::fragment<wmma::accumulator, 16, 16, 16, float> oacc[2][2];
    #pragma unroll
    for (int i = 0; i < 2; i++)
        #pragma unroll
        for (int j = 0; j < 2; j++) wmma::fill_fragment(oacc[i][j], 0.0f);

    for (int kt = 0; kt < L / 64; kt++) {
        #pragma unroll
        for (int i = 0; i < 8; i++) {
            int idx = tid + i * 128;
            int row = idx >> 4, c4 = (idx & 15) * 4;
            float4 tv = *(const float4*)(vb + (size_t)(kt * 64 + row) * (NH * HD) + c4);
            st_half4(&sKV[row * LDT + c4], tv);
        }
        __syncthreads();
        #pragma unroll
        for (int k0 = 0; k0 < 64; k0 += 16) {
            wmma::fragment<wmma::matrix_a, 16, 16, 16, __half, wmma::row_major> af[2];
            wmma::fragment<wmma::matrix_b, 16, 16, 16, __half, wmma::row_major> bf[2];
            #pragma unroll
            for (int i = 0; i < 2; i++)
                wmma::load_matrix_sync(af[i],
                    &sSh[(size_t)(wm * 32 + i * 16) * (2 * FA_LDS) + kt * 64 + k0], 2 * FA_LDS);
            #pragma unroll
            for (int j = 0; j < 2; j++)
                wmma::load_matrix_sync(bf[j], &sKV[k0 * LDT + wn * 32 + j * 16], LDT);
            #pragma unroll
            for (int i = 0; i < 2; i++)
                #pragma unroll
                for (int j = 0; j < 2; j++)
                    wmma::mma_sync(oacc[i][j], af[i], bf[j], oacc[i][j]);
        }
        __syncthreads();
    }

    int row0 = mt * 64 + wm * 32;
    int col0 = wn * 32;
    #pragma unroll
    for (int i = 0; i < 2; i++)
        #pragma unroll
        for (int j = 0; j < 2; j++)
            wmma::store_matrix_sync(ob + (size_t)(row0 + i * 16) * (NH * HD) + col0 + j * 16,
                                    oacc[i][j], NH * HD, wmma::mem_row_major);
}

// ---------------- final mean over tokens ----------------
__global__ void mean_kernel(const float* __restrict__ y, float* __restrict__ out) {
    int n = blockIdx.x;
    int c = threadIdx.x;   // 768
    float s = 0.f;
    for (int l = 0; l < L; l++) s += y[((size_t)n * L + l) * W + c];
    out[n * W + c] = s * (1.0f / (float)L);
}

// ---------------- host orchestration ----------------
extern "C" void kernel_launch(void* const* d_in, const int* in_sizes, int n_in,
                              void* d_out, int out_size) {
    const float* image   = (const float*)d_in[0];
    const float* ckern   = (const float*)d_in[1];
    const float* cbias   = (const float*)d_in[2];
    const float* ln1s    = (const float*)d_in[3];
    const float* ln1b    = (const float*)d_in[4];
    const float* wq      = (const float*)d_in[5];
    const float* bq      = (const float*)d_in[6];
    const float* wk      = (const float*)d_in[7];
    const float* bk      = (const float*)d_in[8];
    const float* wv      = (const float*)d_in[9];
    const float* bv      = (const float*)d_in[10];
    const float* wo      = (const float*)d_in[11];
    const float* bo      = (const float*)d_in[12];
    const float* ln2s    = (const float*)d_in[13];
    const float* ln2b    = (const float*)d_in[14];
    const float* w1      = (const float*)d_in[15];
    const float* b1      = (const float*)d_in[16];
    const float* w2      = (const float*)d_in[17];
    const float* b2      = (const float*)d_in[18];
    const float* lnfs    = (const float*)d_in[19];
    const float* lnfb    = (const float*)d_in[20];
    float* out = (float*)d_out;

    float *x, *y, *q, *k, *v, *o, *hbuf;
    cudaGetSymbolAddress((void**)&x, g_x);
    cudaGetSymbolAddress((void**)&y, g_y);
    cudaGetSymbolAddress((void**)&q, g_q);
    cudaGetSymbolAddress((void**)&k, g_k);
    cudaGetSymbolAddress((void**)&v, g_v);
    cudaGetSymbolAddress((void**)&o, g_o);
    cudaGetSymbolAddress((void**)&hbuf, g_h);

    cudaFuncSetAttribute(attn_fused, cudaFuncAttributeMaxDynamicSharedMemorySize, FA_SMEM);

    const size_t WW = (size_t)W * W;
    const size_t WM = (size_t)W * MLP;

    // patch embed: im2col + GEMM
    {
        int total = M_ROWS * W;
        im2col_kernel<<<(total + 255) / 256, 256>>>(image, y);
        dim3 gg(W / GBN, M_ROWS / GBM);
        gemm_tc<0><<<gg, 256>>>(y, ckern, cbias, nullptr, x, M_ROWS, W, W);
    }
    rope_cache_kernel<<<(L * 16 + 255) / 256, 256>>>();

    dim3 gw(W / GBN, M_ROWS / GBM);        // 768-wide GEMMs: (6, 36)
    dim3 gqkv(W / GBN, M_ROWS / GBM, 3);   // fused QKV: (6, 36, 3)
    dim3 gm(MLP / GBN, M_ROWS / GBM);      // 3072-wide GEMM: (24, 36)
    dim3 gat(L / 64, NB * NH);             // fused attention: (9, 96)

    for (int l = 0; l < DPT; l++) {
        ln_warp<<<M_ROWS / 8, 256>>>(x, ln1s + l * W, ln1b + l * W, y);
        gemm_qkv<<<gqkv, 256>>>(y, wq + l * WW, wk + l * WW, wv + l * WW,
                                bq + l * W, bk + l * W, bv + l * W,
                                q, k, v, M_ROWS, W, W);
        attn_fused<<<gat, 128, FA_SMEM>>>(q, k, v, o);
        // x = x + (o @ wo + bo)
        gemm_tc<2><<<gw, 256>>>(o, wo + l * WW, bo + l * W, x, x, M_ROWS, W, W);
        ln_warp<<<M_ROWS / 8, 256>>>(x, ln2s + l * W, ln2b + l * W, y);
        gemm_tc<1><<<gm, 256>>>(y, w1 + l * WM, b1 + l * MLP, nullptr, hbuf, M_ROWS, MLP, W);
        gemm_tc<2><<<gw, 256>>>(hbuf, w2 + l * WM, b2 + l * W, x, x, M_ROWS, W, MLP);
    }

    ln_warp<<<M_ROWS / 8, 256>>>(x, lnfs, lnfb, y);
    mean_kernel<<<NB, W>>>(y, out);
}

// round 15
// speedup vs baseline: 1.1184x; 1.0787x over previous
#include <cuda_runtime.h>
#include <cuda_fp16.h>
#include <cuda_bf16.h>
#include <mma.h>
#include <cstdint>

using namespace nvcuda;

// ---------------- problem constants ----------------
#define NB 8            // batch
#define HW 384
#define CIN 3
#define PATCH 16
#define GRID 24         // 384/16
#define L 576           // GRID*GRID tokens
#define W 768           // width
#define DPT 4           // depth
#define NH 12           // heads
#define HD 64           // head dim
#define MLP 3072
#define M_ROWS (NB*L)   // 4608

// ---------------- scratch (device globals; no allocation allowed) ----------
__device__ float g_x[M_ROWS * W];     // residual stream
__device__ float g_y[M_ROWS * W];     // LN output / im2col buffer
__device__ float g_q[M_ROWS * W];
__device__ float g_k[M_ROWS * W];
__device__ float g_v[M_ROWS * W];
__device__ float g_o[M_ROWS * W];
__device__ float g_h[M_ROWS * MLP];   // MLP hidden
__device__ float g_rope[4][L][16];    // cosx,sinx,cosy,siny

// ---------------- helpers ----------------
__device__ __forceinline__ float gelu_tanh(float x) {
    const float k0 = 0.7978845608028654f;   // sqrt(2/pi)
    float x3 = x * x * x;
    return 0.5f * x * (1.0f + tanhf(k0 * (x + 0.044715f * x3)));
}

// store 4 floats as 4 fp16 (RN) at an 8B-aligned smem address
__device__ __forceinline__ void st_half4(__half* d, float4 t) {
    *(__half2*)(d)     = __floats2half2_rn(t.x, t.y);
    *(__half2*)(d + 2) = __floats2half2_rn(t.z, t.w);
}

// ---------------- im2col: image(NHWC) -> rows [NB*L, 768] -------------------
__global__ void im2col_kernel(const float* __restrict__ img, float* __restrict__ out) {
    int idx = blockIdx.x * blockDim.x + threadIdx.x;
    const int total = M_ROWS * W;
    if (idx >= total) return;
    int col = idx % W;
    int rest = idx / W;
    int p = rest % L;
    int n = rest / L;
    int c = col % CIN;
    int ij = col / CIN;
    int j = ij % PATCH;
    int i = ij / PATCH;
    int px = p % GRID, py = p / GRID;
    out[idx] = img[(((size_t)n * HW + (py * PATCH + i)) * HW + (px * PATCH + j)) * CIN + c];
}

// ---------------- RoPE cache ----------------
__global__ void rope_cache_kernel() {
    int idx = blockIdx.x * blockDim.x + threadIdx.x;
    if (idx >= L * 16) return;
    int l = idx / 16, f = idx % 16;
    int px = l % GRID, py = l / GRID;
    float u = (px + 0.5f) / (float)GRID;
    float v = (py + 0.5f) / (float)GRID;
    float fr = (float)f / (15.0f + 1e-9f);
    float inv = expf(-fr * 9.210340371976184f);  // 10000^-fr
    float ax = u * inv, ay = v * inv;
    g_rope[0][l][f] = cosf(ax);
    g_rope[1][l][f] = sinf(ax);
    g_rope[2][l][f] = cosf(ay);
    g_rope[3][l][f] = sinf(ay);
}

// ---------------- LayerNorm: warp per row, C = 768 fixed ----------------
__global__ void ln_warp(const float* __restrict__ x, const float* __restrict__ sc,
                        const float* __restrict__ bi, float* __restrict__ y) {
    int wid = threadIdx.x >> 5, lane = threadIdx.x & 31;
    int row = blockIdx.x * 8 + wid;
    const float4* xr = (const float4*)(x + (size_t)row * W);
    float4 v[6];
    float s1 = 0.f, s2 = 0.f;
    #pragma unroll
    for (int i = 0; i < 6; i++) {
        v[i] = xr[lane + 32 * i];
        s1 += v[i].x + v[i].y + v[i].z + v[i].w;
        s2 += v[i].x * v[i].x + v[i].y * v[i].y + v[i].z * v[i].z + v[i].w * v[i].w;
    }
    #pragma unroll
    for (int o = 16; o > 0; o >>= 1) {
        s1 += __shfl_xor_sync(0xffffffffu, s1, o);
        s2 += __shfl_xor_sync(0xffffffffu, s2, o);
    }
    float mean = s1 * (1.0f / W);
    float var  = s2 * (1.0f / W) - mean * mean;
    float rstd = rsqrtf(var + 1e-6f);
    float4* yr = (float4*)(y + (size_t)row * W);
    const float4* s4 = (const float4*)sc;
    const float4* b4 = (const float4*)bi;
    #pragma unroll
    for (int i = 0; i < 6; i++) {
        int idx = lane + 32 * i;
        float4 sv = s4[idx], bv = b4[idx], o;
        o.x = (v[i].x - mean) * rstd * sv.x + bv.x;
        o.y = (v[i].y - mean) * rstd * sv.y + bv.y;
        o.z = (v[i].z - mean) * rstd * sv.z + bv.z;
        o.w = (v[i].w - mean) * rstd * sv.w + bv.w;
        yr[idx] = o;
    }
}

// ---------------- shared GEMM tile params ----------------
#define GBM 128
#define GBN 128
#define GBK 32
#define LDA_S 40    // halves; 80B row stride (16B-multiple)
#define LDB_S 136   // halves; 272B row stride

// double-buffered mainloop: ONE __syncthreads per k-tile.
// iteration kt: prefetch regs(kt+1) -> compute stage kt&1 -> store stage kt&1^1 -> sync
#define GEMM_MAINLOOP(Aptr, Bptr)                                                        \
    float4 pa[4], pb[4];                                                                 \
    _Pragma("unroll")                                                                    \
    for (int i = 0; i < 4; i++) {                                                        \
        int idx = tid + i * 256;                                                         \
        pa[i] = *(const float4*)(Aptr + (size_t)(row0 + (idx >> 3)) * K + ((idx & 7) * 4)); \
        pb[i] = *(const float4*)(Bptr + (size_t)(idx >> 5) * N + col0 + ((idx & 31) * 4));  \
    }                                                                                    \
    _Pragma("unroll")                                                                    \
    for (int i = 0; i < 4; i++) {                                                        \
        int idx = tid + i * 256;                                                         \
        st_half4(&sA[0][(idx >> 3) * LDA_S + (idx & 7) * 4], pa[i]);                     \
        st_half4(&sB[0][(idx >> 5) * LDB_S + (idx & 31) * 4], pb[i]);                    \
    }                                                                                    \
    __syncthreads();                                                                     \
    int KT = K / GBK;                                                                    \
    for (int kt = 0; kt < KT; kt++) {                                                    \
        int cur = kt & 1;                                                                \
        if (kt + 1 < KT) {                                                               \
            int k0 = (kt + 1) * GBK;                                                     \
            _Pragma("unroll")                                                            \
            for (int i = 0; i < 4; i++) {                                                \
                int idx = tid + i * 256;                                                 \
                pa[i] = *(const float4*)(Aptr + (size_t)(row0 + (idx >> 3)) * K + k0 + ((idx & 7) * 4)); \
                pb[i] = *(const float4*)(Bptr + (size_t)(k0 + (idx >> 5)) * N + col0 + ((idx & 31) * 4)); \
            }                                                                            \
        }                                                                                \
        _Pragma("unroll")                                                                \
        for (int ks = 0; ks < 2; ks++) {                                                 \
            wmma::fragment<wmma::matrix_a, 16, 16, 16, __half, wmma::row_major> af[4];   \
            wmma::fragment<wmma::matrix_b, 16, 16, 16, __half, wmma::row_major> bf[2];   \
            _Pragma("unroll")                                                            \
            for (int i = 0; i < 4; i++)                                                  \
                wmma::load_matrix_sync(af[i], &sA[cur][(warp_m * 64 + i * 16) * LDA_S + ks * 16], LDA_S); \
            _Pragma("unroll")                                                            \
            for (int j = 0; j < 2; j++)                                                  \
                wmma::load_matrix_sync(bf[j], &sB[cur][(ks * 16) * LDB_S + warp_n * 32 + j * 16], LDB_S); \
            _Pragma("unroll")                                                            \
            for (int i = 0; i < 4; i++)                                                  \
                _Pragma("unroll")                                                        \
                for (int j = 0; j < 2; j++)                                              \
                    wmma::mma_sync(acc[i][j], af[i], bf[j], acc[i][j]);                  \
        }                                                                                \
        if (kt + 1 < KT) {                                                               \
            _Pragma("unroll")                                                            \
            for (int i = 0; i < 4; i++) {                                                \
                int idx = tid + i * 256;                                                 \
                st_half4(&sA[cur ^ 1][(idx >> 3) * LDA_S + (idx & 7) * 4], pa[i]);       \
                st_half4(&sB[cur ^ 1][(idx >> 5) * LDB_S + (idx & 31) * 4], pb[i]);      \
            }                                                                            \
        }                                                                                \
        __syncthreads();                                                                 \
    }

// ---------------- generic fp16 GEMM with fused epilogue ---------------------
// C[M,N] = A[M,K] @ B[K,N] + bias[N]   (MODE 0)
//          gelu(...)                   (MODE 1)
//          ... + R[M,N]                (MODE 2)
template <int MODE>
__global__ __launch_bounds__(256, 2) void gemm_tc(
        const float* __restrict__ A, const float* __restrict__ B,
        const float* __restrict__ bias, const float* __restrict__ R,
        float* __restrict__ C, int M, int N, int K) {
    __shared__ __align__(16) __half sA[2][GBM * LDA_S];   // 2 x 10240 B
    __shared__ __align__(16) __half sB[2][GBK * LDB_S];   // 2 x  8704 B

    int tid = threadIdx.x;           // 256
    int wid = tid >> 5, lane = tid & 31;
    int warp_m = wid >> 2;           // 0..1
    int warp_n = wid & 3;            // 0..3
    int row0 = blockIdx.y * GBM, col0 = blockIdx.x * GBN;

    wmma::fragment<wmma::accumulator, 16, 16, 16, float> acc[4][2];
    #pragma unroll
    for (int i = 0; i < 4; i++)
        #pragma unroll
        for (int j = 0; j < 2; j++)
            wmma::fill_fragment(acc[i][j], 0.0f);

    GEMM_MAINLOOP(A, B)

    // epilogue: stage each 16x16 frag through per-warp smem patch (alias sA)
    float* stage = reinterpret_cast<float*>(&sA[0][0]) + wid * 272;
    int r = lane >> 1, c0 = (lane & 1) * 8;
    #pragma unroll
    for (int i = 0; i < 4; i++) {
        #pragma unroll
        for (int j = 0; j < 2; j++) {
            __syncwarp();
            wmma::store_matrix_sync(stage, acc[i][j], 16, wmma::mem_row_major);
            __syncwarp();
            int m = row0 + warp_m * 64 + i * 16 + r;
            int n = col0 + warp_n * 32 + j * 16 + c0;
            float bb[8];
            *(float4*)(bb)     = *(const float4*)(bias + n);
            *(float4*)(bb + 4) = *(const float4*)(bias + n + 4);
            float out[8];
            #pragma unroll
            for (int t = 0; t < 8; t++) out[t] = stage[r * 16 + c0 + t] + bb[t];
            if (MODE == 1) {
                #pragma unroll
                for (int t = 0; t < 8; t++) out[t] = gelu_tanh(out[t]);
            }
            if (MODE == 2) {
                float rr[8];
                *(float4*)(rr)     = *(const float4*)(R + (size_t)m * N + n);
                *(float4*)(rr + 4) = *(const float4*)(R + (size_t)m * N + n + 4);
                #pragma unroll
                for (int t = 0; t < 8; t++) out[t] += rr[t];
            }
            *(float4*)(C + (size_t)m * N + n)     = *(float4*)(out);
            *(float4*)(C + (size_t)m * N + n + 4) = *(float4*)(out + 4);
        }
    }
}

// ---------------- fused QKV GEMM: z selects {q,k,v}; rope fused for q,k -----
__global__ __launch_bounds__(256, 2) void gemm_qkv(
        const float* __restrict__ A,
        const float* __restrict__ Bq, const float* __restrict__ Bk, const float* __restrict__ Bv,
        const float* __restrict__ bq, const float* __restrict__ bk, const float* __restrict__ bv,
        float* __restrict__ Cq, float* __restrict__ Ck, float* __restrict__ Cv,
        int M, int N, int K) {
    __shared__ __align__(16) __half sA[2][GBM * LDA_S];
    __shared__ __align__(16) __half sB[2][GBK * LDB_S];

    int tid = threadIdx.x;
    int wid = tid >> 5, lane = tid & 31;
    int warp_m = wid >> 2;
    int warp_n = wid & 3;
    int row0 = blockIdx.y * GBM, col0 = blockIdx.x * GBN;
    int z = blockIdx.z;
    const float* B    = (z == 0) ? Bq : (z == 1) ? Bk : Bv;
    const float* bias = (z == 0) ? bq : (z == 1) ? bk : bv;
    float* C          = (z == 0) ? Cq : (z == 1) ? Ck : Cv;
    bool do_rope = (z < 2);

    wmma::fragment<wmma::accumulator, 16, 16, 16, float> acc[4][2];
    #pragma unroll
    for (int i = 0; i < 4; i++)
        #pragma unroll
        for (int j = 0; j < 2; j++)
            wmma::fill_fragment(acc[i][j], 0.0f);

    GEMM_MAINLOOP(A, B)

    // epilogue with fused RoPE: each thread owns 8 consecutive cols = 4 pairs
    float* stage = reinterpret_cast<float*>(&sA[0][0]) + wid * 272;
    int r = lane >> 1, c0 = (lane & 1) * 8;
    #pragma unroll
    for (int i = 0; i < 4; i++) {
        #pragma unroll
        for (int j = 0; j < 2; j++) {
            __syncwarp();
            wmma::store_matrix_sync(stage, acc[i][j], 16, wmma::mem_row_major);
            __syncwarp();
            int m = row0 + warp_m * 64 + i * 16 + r;
            int n = col0 + warp_n * 32 + j * 16 + c0;
            float bb[8];
            *(float4*)(bb)     = *(const float4*)(bias + n);
            *(float4*)(bb + 4) = *(const float4*)(bias + n + 4);
            float out[8];
            #pragma unroll
            for (int t = 0; t < 8; t++) out[t] = stage[r * 16 + c0 + t] + bb[t];
            if (do_rope) {
                int l = m % L;           // token index
                int d0 = n & 63;         // dim within head (multiple of 8)
                #pragma unroll
                for (int t = 0; t < 8; t += 2) {
                    int pair = (d0 + t) >> 1;      // 0..31
                    int f = pair & 15;
                    int hi = pair >> 4;            // 0: x-rope, 1: y-rope
                    float cc = g_rope[hi ? 2 : 0][l][f];
                    float ss = g_rope[hi ? 3 : 1][l][f];
                    float xv = out[t], yv = out[t + 1];
                    out[t]     = xv * cc - yv * ss;
                    out[t + 1] = xv * ss + yv * cc;
                }
            }
            *(float4*)(C + (size_t)m * N + n)     = *(float4*)(out);
            *(float4*)(C + (size_t)m * N + n + 4) = *(float4*)(out + 4);
        }
    }
}

// ---------------- fused attention: QK^T + softmax + P@V, 256 threads --------
// One CTA per (64-query tile, n*NH+h). All 576 key scores live in smem.
// 8 warps: 4x2 layout over the 64x64 tiles (warp = 16 rows x 32 cols).
#define LDT 72        // halves; 144B row stride
#define FA_LDS 584    // floats per score row (584 % 32 == 8)
#define FA_SMEM (64 * FA_LDS * 4 + 2 * 64 * LDT * 2)   // 167936

__global__ __launch_bounds__(256) void attn_fused(
        const float* __restrict__ q, const float* __restrict__ k,
        const float* __restrict__ v, float* __restrict__ o) {
    extern __shared__ __align__(16) unsigned char fsm[];
    float*  sS  = reinterpret_cast<float*>(fsm);
    __half* sSh = reinterpret_cast<__half*>(fsm);           // half view of sS
    __half* sQ  = reinterpret_cast<__half*>(fsm + 64 * FA_LDS * 4);
    __half* sKV = sQ + 64 * LDT;

    int mt = blockIdx.x;          // query tile 0..8
    int nh = blockIdx.y;          // n*NH + h
    int n = nh / NH, h = nh % NH;
    const float* qb = q + ((size_t)n * L * NH + h) * HD;    // row stride 768
    const float* kb = k + ((size_t)n * L * NH + h) * HD;
    const float* vb = v + ((size_t)n * L * NH + h) * HD;
    float* ob = o + ((size_t)n * L * NH + h) * HD;

    int tid = threadIdx.x;        // 256
    int wid = tid >> 5, lane = tid & 31;
    int wm = wid >> 1, wn = wid & 1;    // 4x2 warp layout: 16-row x 32-col per warp

    // ---- load Q tile (1024 float4 over 256 threads = 4 iters) ----
    #pragma unroll
    for (int i = 0; i < 4; i++) {
        int idx = tid + i * 256;
        int row = idx >> 4, c4 = (idx & 15) * 4;
        float4 tq = *(const float4*)(qb + (size_t)(mt * 64 + row) * (NH * HD) + c4);
        st_half4(&sQ[row * LDT + c4], tq);
    }

    // ---- phase 1: S = Q K^T for all 9 key tiles ----
    for (int kt = 0; kt < L / 64; kt++) {
        __syncthreads();   // protect sKV reuse (and Q store on first iter)
        #pragma unroll
        for (int i = 0; i < 4; i++) {
            int idx = tid + i * 256;
            int row = idx >> 4, c4 = (idx & 15) * 4;
            float4 tk = *(const float4*)(kb + (size_t)(kt * 64 + row) * (NH * HD) + c4);
            st_half4(&sKV[row * LDT + c4], tk);
        }
        __syncthreads();
        wmma::fragment<wmma::accumulator, 16, 16, 16, float> acc[2];
        #pragma unroll
        for (int j = 0; j < 2; j++) wmma::fill_fragment(acc[j], 0.0f);
        #pragma unroll
        for (int k0 = 0; k0 < HD; k0 += 16) {
            wmma::fragment<wmma::matrix_a, 16, 16, 16, __half, wmma::row_major> af;
            wmma::fragment<wmma::matrix_b, 16, 16, 16, __half, wmma::col_major> bf[2];
            wmma::load_matrix_sync(af, &sQ[(wm * 16) * LDT + k0], LDT);
            #pragma unroll
            for (int j = 0; j < 2; j++)
                wmma::load_matrix_sync(bf[j], &sKV[(wn * 32 + j * 16) * LDT + k0], LDT);
            #pragma unroll
            for (int j = 0; j < 2; j++)
                wmma::mma_sync(acc[j], af, bf[j], acc[j]);
        }
        #pragma unroll
        for (int j = 0; j < 2; j++)
            wmma::store_matrix_sync(&sS[(wm * 16) * FA_LDS + kt * 64 + wn * 32 + j * 16],
                                    acc[j], FA_LDS, wmma::mem_row_major);
    }
    __syncthreads();   // all S tiles written

    // ---- phase 2: softmax per row (warp w owns rows 8w..8w+7) ----
    for (int rr = 0; rr < 8; rr++) {
        int row = wid * 8 + rr;
        float* rowp = sS + (size_t)row * FA_LDS;
        float r[18];
        float m = -1e30f;
        #pragma unroll
        for (int i = 0; i < 18; i++) { r[i] = rowp[lane + 32 * i]; m = fmaxf(m, r[i]); }
        #pragma unroll
        for (int off = 16; off > 0; off >>= 1) m = fmaxf(m, __shfl_xor_sync(0xffffffffu, m, off));
        float s = 0.f;
        #pragma unroll
        for (int i = 0; i < 18; i++) { r[i] = __expf(0.125f * (r[i] - m)); s += r[i]; }
        #pragma unroll
        for (int off = 16; off > 0; off >>= 1) s += __shfl_xor_sync(0xffffffffu, s, off);
        float inv = 1.0f / s;
        __syncwarp();   // all lanes done reading fp32 row before fp16 overwrite
        __half* rowh = sSh + (size_t)row * (2 * FA_LDS);
        #pragma unroll
        for (int i = 0; i < 18; i++) rowh[lane + 32 * i] = __float2half_rn(r[i] * inv);
    }
    __syncthreads();   // probs visible to all warps

    // ---- phase 3: O = P V, accumulate over 9 value tiles ----
    wmma::fragment<wmma::accumulator, 16, 16, 16, float> oacc[2];
    #pragma unroll
    for (int j = 0; j < 2; j++) wmma::fill_fragment(oacc[j], 0.0f);

    for (int kt = 0; kt < L / 64; kt++) {
        #pragma unroll
        for (int i = 0; i < 4; i++) {
            int idx = tid + i * 256;
            int row = idx >> 4, c4 = (idx & 15) * 4;
            float4 tv = *(const float4*)(vb + (size_t)(kt * 64 + row) * (NH * HD) + c4);
            st_half4(&sKV[row * LDT + c4], tv);
        }
        __syncthreads();
        #pragma unroll
        for (int k0 = 0; k0 < 64; k0 += 16) {
            wmma::fragment<wmma::matrix_a, 16, 16, 16, __half, wmma::row_major> af;
            wmma::fragment<wmma::matrix_b, 16, 16, 16, __half, wmma::row_major> bf[2];
            wmma::load_matrix_sync(af,
                &sSh[(size_t)(wm * 16) * (2 * FA_LDS) + kt * 64 + k0], 2 * FA_LDS);
            #pragma unroll
            for (int j = 0; j < 2; j++)
                wmma::load_matrix_sync(bf[j], &sKV[k0 * LDT + wn * 32 + j * 16], LDT);
            #pragma unroll
            for (int j = 0; j < 2; j++)
                wmma::mma_sync(oacc[j], af, bf[j], oacc[j]);
        }
        __syncthreads();   // V tile consumed before next overwrite
    }

    int row0 = mt * 64 + wm * 16;
    int col0 = wn * 32;
    #pragma unroll
    for (int j = 0; j < 2; j++)
        wmma::store_matrix_sync(ob + (size_t)row0 * (NH * HD) + col0 + j * 16,
                                oacc[j], NH * HD, wmma::mem_row_major);
}

// ---------------- final mean over tokens ----------------
__global__ void mean_kernel(const float* __restrict__ y, float* __restrict__ out) {
    int n = blockIdx.x;
    int c = threadIdx.x;   // 768
    float s = 0.f;
    for (int l = 0; l < L; l++) s += y[((size_t)n * L + l) * W + c];
    out[n * W + c] = s * (1.0f / (float)L);
}

// ---------------- host orchestration ----------------
extern "C" void kernel_launch(void* const* d_in, const int* in_sizes, int n_in,
                              void* d_out, int out_size) {
    const float* image   = (const float*)d_in[0];
    const float* ckern   = (const float*)d_in[1];
    const float* cbias   = (const float*)d_in[2];
    const float* ln1s    = (const float*)d_in[3];
    const float* ln1b    = (const float*)d_in[4];
    const float* wq      = (const float*)d_in[5];
    const float* bq      = (const float*)d_in[6];
    const float* wk      = (const float*)d_in[7];
    const float* bk      = (const float*)d_in[8];
    const float* wv      = (const float*)d_in[9];
    const float* bv      = (const float*)d_in[10];
    const float* wo      = (const float*)d_in[11];
    const float* bo      = (const float*)d_in[12];
    const float* ln2s    = (const float*)d_in[13];
    const float* ln2b    = (const float*)d_in[14];
    const float* w1      = (const float*)d_in[15];
    const float* b1      = (const float*)d_in[16];
    const float* w2      = (const float*)d_in[17];
    const float* b2      = (const float*)d_in[18];
    const float* lnfs    = (const float*)d_in[19];
    const float* lnfb    = (const float*)d_in[20];
    float* out = (float*)d_out;

    float *x, *y, *q, *k, *v, *o, *hbuf;
    cudaGetSymbolAddress((void**)&x, g_x);
    cudaGetSymbolAddress((void**)&y, g_y);
    cudaGetSymbolAddress((void**)&q, g_q);
    cudaGetSymbolAddress((void**)&k, g_k);
    cudaGetSymbolAddress((void**)&v, g_v);
    cudaGetSymbolAddress((void**)&o, g_o);
    cudaGetSymbolAddress((void**)&hbuf, g_h);

    cudaFuncSetAttribute(attn_fused, cudaFuncAttributeMaxDynamicSharedMemorySize, FA_SMEM);

    const size_t WW = (size_t)W * W;
    const size_t WM = (size_t)W * MLP;

    // patch embed: im2col + GEMM
    {
        int total = M_ROWS * W;
        im2col_kernel<<<(total + 255) / 256, 256>>>(image, y);
        dim3 gg(W / GBN, M_ROWS / GBM);
        gemm_tc<0><<<gg, 256>>>(y, ckern, cbias, nullptr, x, M_ROWS, W, W);
    }
    rope_cache_kernel<<<(L * 16 + 255) / 256, 256>>>();

    dim3 gw(W / GBN, M_ROWS / GBM);        // 768-wide GEMMs: (6, 36)
    dim3 gqkv(W / GBN, M_ROWS / GBM, 3);   // fused QKV: (6, 36, 3)
    dim3 gm(MLP / GBN, M_ROWS / GBM);      // 3072-wide GEMM: (24, 36)
    dim3 gat(L / 64, NB * NH);             // fused attention: (9, 96)

    for (int l = 0; l < DPT; l++) {
        ln_warp<<<M_ROWS / 8, 256>>>(x, ln1s + l * W, ln1b + l * W, y);
        gemm_qkv<<<gqkv, 256>>>(y, wq + l * WW, wk + l * WW, wv + l * WW,
                                bq + l * W, bk + l * W, bv + l * W,
                                q, k, v, M_ROWS, W, W);
        attn_fused<<<gat, 256, FA_SMEM>>>(q, k, v, o);
        // x = x + (o @ wo + bo)
        gemm_tc<2><<<gw, 256>>>(o, wo + l * WW, bo + l * W, x, x, M_ROWS, W, W);
        ln_warp<<<M_ROWS / 8, 256>>>(x, ln2s + l * W, ln2b + l * W, y);
        gemm_tc<1><<<gm, 256>>>(y, w1 + l * WM, b1 + l * MLP, nullptr, hbuf, M_ROWS, MLP, W);
        gemm_tc<2><<<gw, 256>>>(hbuf, w2 + l * WM, b2 + l * W, x, x, M_ROWS, W, MLP);
    }

    ln_warp<<<M_ROWS / 8, 256>>>(x, lnfs, lnfb, y);
    mean_kernel<<<NB, W>>>(y, out);
}

// round 16
// speedup vs baseline: 1.3166x; 1.1772x over previous
#include <cuda_runtime.h>
#include <cuda_fp16.h>
#include <cuda_bf16.h>
#include <mma.h>
#include <cstdint>

using namespace nvcuda;

// ---------------- problem constants ----------------
#define NB 8            // batch
#define HW 384
#define CIN 3
#define PATCH 16
#define GRID 24         // 384/16
#define L 576           // GRID*GRID tokens
#define W 768           // width
#define DPT 4           // depth
#define NH 12           // heads
#define HD 64           // head dim
#define MLP 3072
#define M_ROWS (NB*L)   // 4608

#define CONV_SZ (PATCH*PATCH*CIN*W)   // 589824 == W*W
#define WM_SZ   (W*MLP)               // 2359296
#define WT_TOTAL (17*CONV_SZ + 8*WM_SZ)   // 28,901,376 halves

// ---------------- scratch (device globals; no allocation allowed) ----------
__device__ float  g_x[M_ROWS * W];      // residual stream (fp32)
__device__ float  g_yf[M_ROWS * W];     // final-LN output (fp32)
__device__ __half g_y[M_ROWS * W];      // LN output / im2col (fp16)
__device__ __half g_q[M_ROWS * W];
__device__ __half g_k[M_ROWS * W];
__device__ __half g_v[M_ROWS * W];
__device__ __half g_o[M_ROWS * W];
__device__ __half g_h[M_ROWS * MLP];    // MLP hidden (fp16)
__device__ __half g_wt[WT_TOTAL];       // fp16 weights
__device__ float  g_rope[4][L][16];     // cosx,sinx,cosy,siny

// ---------------- helpers ----------------
__device__ __forceinline__ float gelu_tanh(float x) {
    const float k0 = 0.7978845608028654f;   // sqrt(2/pi)
    float x3 = x * x * x;
    return 0.5f * x * (1.0f + tanhf(k0 * (x + 0.044715f * x3)));
}

// write 8 fp32 values as 8 consecutive fp16 (one 16B store)
__device__ __forceinline__ void store_row8(__half* C, const float* v) {
    __align__(16) __half t[8];
    #pragma unroll
    for (int i = 0; i < 8; i++) t[i] = __float2half_rn(v[i]);
    *(float4*)C = *(float4*)t;
}
// write 8 fp32 values as fp32 (two 16B stores)
__device__ __forceinline__ void store_row8(float* C, const float* v) {
    *(float4*)C       = *(const float4*)v;
    *(float4*)(C + 4) = *(const float4*)(v + 4);
}

// ---------------- weight fp16 conversion (once per launch) ------------------
struct CJob { const float* s; __half* d; int n4; };
struct CJobs { CJob j[7]; };

__global__ void cvt_weights(CJobs jobs) {
    CJob jb = jobs.j[blockIdx.y];
    const float4* s4 = (const float4*)jb.s;
    for (int i = blockIdx.x * blockDim.x + threadIdx.x; i < jb.n4;
         i += gridDim.x * blockDim.x) {
        float4 t = s4[i];
        __half2 h0 = __floats2half2_rn(t.x, t.y);
        __half2 h1 = __floats2half2_rn(t.z, t.w);
        *(__half2*)(jb.d + i * 4)     = h0;
        *(__half2*)(jb.d + i * 4 + 2) = h1;
    }
}

// ---------------- im2col: image(NHWC) -> rows [NB*L, 768] fp16 --------------
__global__ void im2col_kernel(const float* __restrict__ img, __half* __restrict__ out) {
    int idx = blockIdx.x * blockDim.x + threadIdx.x;
    const int total = M_ROWS * W;
    if (idx >= total) return;
    int col = idx % W;
    int rest = idx / W;
    int p = rest % L;
    int n = rest / L;
    int c = col % CIN;
    int ij = col / CIN;
    int j = ij % PATCH;
    int i = ij / PATCH;
    int px = p % GRID, py = p / GRID;
    out[idx] = __float2half_rn(
        img[(((size_t)n * HW + (py * PATCH + i)) * HW + (px * PATCH + j)) * CIN + c]);
}

// ---------------- RoPE cache ----------------
__global__ void rope_cache_kernel() {
    int idx = blockIdx.x * blockDim.x + threadIdx.x;
    if (idx >= L * 16) return;
    int l = idx / 16, f = idx % 16;
    int px = l % GRID, py = l / GRID;
    float u = (px + 0.5f) / (float)GRID;
    float v = (py + 0.5f) / (float)GRID;
    float fr = (float)f / (15.0f + 1e-9f);
    float inv = expf(-fr * 9.210340371976184f);  // 10000^-fr
    float ax = u * inv, ay = v * inv;
    g_rope[0][l][f] = cosf(ax);
    g_rope[1][l][f] = sinf(ax);
    g_rope[2][l][f] = cosf(ay);
    g_rope[3][l][f] = sinf(ay);
}

// ---------------- LayerNorm: warp per row, C = 768 fixed ----------------
template <typename OutT>
__global__ void ln_warp(const float* __restrict__ x, const float* __restrict__ sc,
                        const float* __restrict__ bi, OutT* __restrict__ y) {
    int wid = threadIdx.x >> 5, lane = threadIdx.x & 31;
    int row = blockIdx.x * 8 + wid;
    const float4* xr = (const float4*)(x + (size_t)row * W);
    float4 v[6];
    float s1 = 0.f, s2 = 0.f;
    #pragma unroll
    for (int i = 0; i < 6; i++) {
        v[i] = xr[lane + 32 * i];
        s1 += v[i].x + v[i].y + v[i].z + v[i].w;
        s2 += v[i].x * v[i].x + v[i].y * v[i].y + v[i].z * v[i].z + v[i].w * v[i].w;
    }
    #pragma unroll
    for (int o = 16; o > 0; o >>= 1) {
        s1 += __shfl_xor_sync(0xffffffffu, s1, o);
        s2 += __shfl_xor_sync(0xffffffffu, s2, o);
    }
    float mean = s1 * (1.0f / W);
    float var  = s2 * (1.0f / W) - mean * mean;
    float rstd = rsqrtf(var + 1e-6f);
    OutT* yrow = y + (size_t)row * W;
    const float4* s4 = (const float4*)sc;
    const float4* b4 = (const float4*)bi;
    #pragma unroll
    for (int i = 0; i < 6; i++) {
        int idx = lane + 32 * i;
        float4 sv = s4[idx], bv = b4[idx];
        float o0 = (v[i].x - mean) * rstd * sv.x + bv.x;
        float o1 = (v[i].y - mean) * rstd * sv.y + bv.y;
        float o2 = (v[i].z - mean) * rstd * sv.z + bv.z;
        float o3 = (v[i].w - mean) * rstd * sv.w + bv.w;
        if (sizeof(OutT) == 2) {
            __half* d = (__half*)yrow + idx * 4;
            *(__half2*)(d)     = __floats2half2_rn(o0, o1);
            *(__half2*)(d + 2) = __floats2half2_rn(o2, o3);
        } else {
            float4* d = (float4*)yrow + idx;
            *d = make_float4(o0, o1, o2, o3);
        }
    }
}

// ---------------- shared GEMM tile params ----------------
#define GBM 128
#define GBN 128
#define GBK 32
#define LDA_S 40    // halves; 80B row stride
#define LDB_S 136   // halves; 272B row stride

// double-buffered mainloop, fp16 global operands, ONE __syncthreads per k-tile
// A tile: 128x32 halves = 512 float4; B tile: 32x128 halves = 512 float4.
#define GEMM_MAINLOOP(Aptr, Bptr)                                                        \
    float4 pa[2], pb[2];                                                                 \
    _Pragma("unroll")                                                                    \
    for (int i = 0; i < 2; i++) {                                                        \
        int idx = tid + i * 256;                                                         \
        pa[i] = *(const float4*)(Aptr + (size_t)(row0 + (idx >> 2)) * K + ((idx & 3) * 8));  \
        pb[i] = *(const float4*)(Bptr + (size_t)(idx >> 4) * N + col0 + ((idx & 15) * 8));   \
    }                                                                                    \
    _Pragma("unroll")                                                                    \
    for (int i = 0; i < 2; i++) {                                                        \
        int idx = tid + i * 256;                                                         \
        *(float4*)&sA[0][(idx >> 2) * LDA_S + (idx & 3) * 8]  = pa[i];                   \
        *(float4*)&sB[0][(idx >> 4) * LDB_S + (idx & 15) * 8] = pb[i];                   \
    }                                                                                    \
    __syncthreads();                                                                     \
    int KT = K / GBK;                                                                    \
    for (int kt = 0; kt < KT; kt++) {                                                    \
        int cur = kt & 1;                                                                \
        if (kt + 1 < KT) {                                                               \
            int k0 = (kt + 1) * GBK;                                                     \
            _Pragma("unroll")                                                            \
            for (int i = 0; i < 2; i++) {                                                \
                int idx = tid + i * 256;                                                 \
                pa[i] = *(const float4*)(Aptr + (size_t)(row0 + (idx >> 2)) * K + k0 + ((idx & 3) * 8)); \
                pb[i] = *(const float4*)(Bptr + (size_t)(k0 + (idx >> 4)) * N + col0 + ((idx & 15) * 8)); \
            }                                                                            \
        }                                                                                \
        _Pragma("unroll")                                                                \
        for (int ks = 0; ks < 2; ks++) {                                                 \
            wmma::fragment<wmma::matrix_a, 16, 16, 16, __half, wmma::row_major> af[4];   \
            wmma::fragment<wmma::matrix_b, 16, 16, 16, __half, wmma::row_major> bf[2];   \
            _Pragma("unroll")                                                            \
            for (int i = 0; i < 4; i++)                                                  \
                wmma::load_matrix_sync(af[i], &sA[cur][(warp_m * 64 + i * 16) * LDA_S + ks * 16], LDA_S); \
            _Pragma("unroll")                                                            \
            for (int j = 0; j < 2; j++)                                                  \
                wmma::load_matrix_sync(bf[j], &sB[cur][(ks * 16) * LDB_S + warp_n * 32 + j * 16], LDB_S); \
            _Pragma("unroll")                                                            \
            for (int i = 0; i < 4; i++)                                                  \
                _Pragma("unroll")                                                        \
                for (int j = 0; j < 2; j++)                                              \
                    wmma::mma_sync(acc[i][j], af[i], bf[j], acc[i][j]);                  \
        }                                                                                \
        if (kt + 1 < KT) {                                                               \
            _Pragma("unroll")                                                            \
            for (int i = 0; i < 2; i++) {                                                \
                int idx = tid + i * 256;                                                 \
                *(float4*)&sA[cur ^ 1][(idx >> 2) * LDA_S + (idx & 3) * 8]  = pa[i];     \
                *(float4*)&sB[cur ^ 1][(idx >> 4) * LDB_S + (idx & 15) * 8] = pb[i];     \
            }                                                                            \
        }                                                                                \
        __syncthreads();                                                                 \
    }

// ---------------- generic fp16-input GEMM with fused epilogue ---------------
// C[M,N] = A[M,K] @ B[K,N] + bias[N]   (MODE 0, OutT=float)
//          gelu(...)                   (MODE 1, OutT=half)
//          ... + R[M,N]                (MODE 2, OutT=float)
template <int MODE, typename OutT>
__global__ __launch_bounds__(256, 2) void gemm_tc(
        const __half* __restrict__ A, const __half* __restrict__ B,
        const float* __restrict__ bias, const float* __restrict__ R,
        OutT* __restrict__ C, int M, int N, int K) {
    __shared__ __align__(16) __half sA[2][GBM * LDA_S];   // 2 x 10240 B
    __shared__ __align__(16) __half sB[2][GBK * LDB_S];   // 2 x  8704 B

    int tid = threadIdx.x;           // 256
    int wid = tid >> 5, lane = tid & 31;
    int warp_m = wid >> 2;           // 0..1
    int warp_n = wid & 3;            // 0..3
    int row0 = blockIdx.y * GBM, col0 = blockIdx.x * GBN;

    wmma::fragment<wmma::accumulator, 16, 16, 16, float> acc[4][2];
    #pragma unroll
    for (int i = 0; i < 4; i++)
        #pragma unroll
        for (int j = 0; j < 2; j++)
            wmma::fill_fragment(acc[i][j], 0.0f);

    GEMM_MAINLOOP(A, B)

    // epilogue: stage each 16x16 frag through per-warp smem patch (alias sA)
    float* stage = reinterpret_cast<float*>(&sA[0][0]) + wid * 272;
    int r = lane >> 1, c0 = (lane & 1) * 8;
    #pragma unroll
    for (int i = 0; i < 4; i++) {
        #pragma unroll
        for (int j = 0; j < 2; j++) {
            __syncwarp();
            wmma::store_matrix_sync(stage, acc[i][j], 16, wmma::mem_row_major);
            __syncwarp();
            int m = row0 + warp_m * 64 + i * 16 + r;
            int n = col0 + warp_n * 32 + j * 16 + c0;
            float bb[8];
            *(float4*)(bb)     = *(const float4*)(bias + n);
            *(float4*)(bb + 4) = *(const float4*)(bias + n + 4);
            float out[8];
            #pragma unroll
            for (int t = 0; t < 8; t++) out[t] = stage[r * 16 + c0 + t] + bb[t];
            if (MODE == 1) {
                #pragma unroll
                for (int t = 0; t < 8; t++) out[t] = gelu_tanh(out[t]);
            }
            if (MODE == 2) {
                float rr[8];
                *(float4*)(rr)     = *(const float4*)(R + (size_t)m * N + n);
                *(float4*)(rr + 4) = *(const float4*)(R + (size_t)m * N + n + 4);
                #pragma unroll
                for (int t = 0; t < 8; t++) out[t] += rr[t];
            }
            store_row8(C + (size_t)m * N + n, out);
        }
    }
}

// ---------------- fused QKV GEMM: z selects {q,k,v}; rope fused for q,k -----
__global__ __launch_bounds__(256, 2) void gemm_qkv(
        const __half* __restrict__ A,
        const __half* __restrict__ Bq, const __half* __restrict__ Bk, const __half* __restrict__ Bv,
        const float* __restrict__ bq, const float* __restrict__ bk, const float* __restrict__ bv,
        __half* __restrict__ Cq, __half* __restrict__ Ck, __half* __restrict__ Cv,
        int M, int N, int K) {
    __shared__ __align__(16) __half sA[2][GBM * LDA_S];
    __shared__ __align__(16) __half sB[2][GBK * LDB_S];

    int tid = threadIdx.x;
    int wid = tid >> 5, lane = tid & 31;
    int warp_m = wid >> 2;
    int warp_n = wid & 3;
    int row0 = blockIdx.y * GBM, col0 = blockIdx.x * GBN;
    int z = blockIdx.z;
    const __half* B   = (z == 0) ? Bq : (z == 1) ? Bk : Bv;
    const float* bias = (z == 0) ? bq : (z == 1) ? bk : bv;
    __half* C         = (z == 0) ? Cq : (z == 1) ? Ck : Cv;
    bool do_rope = (z < 2);

    wmma::fragment<wmma::accumulator, 16, 16, 16, float> acc[4][2];
    #pragma unroll
    for (int i = 0; i < 4; i++)
        #pragma unroll
        for (int j = 0; j < 2; j++)
            wmma::fill_fragment(acc[i][j], 0.0f);

    GEMM_MAINLOOP(A, B)

    // epilogue with fused RoPE: each thread owns 8 consecutive cols = 4 pairs
    float* stage = reinterpret_cast<float*>(&sA[0][0]) + wid * 272;
    int r = lane >> 1, c0 = (lane & 1) * 8;
    #pragma unroll
    for (int i = 0; i < 4; i++) {
        #pragma unroll
        for (int j = 0; j < 2; j++) {
            __syncwarp();
            wmma::store_matrix_sync(stage, acc[i][j], 16, wmma::mem_row_major);
            __syncwarp();
            int m = row0 + warp_m * 64 + i * 16 + r;
            int n = col0 + warp_n * 32 + j * 16 + c0;
            float bb[8];
            *(float4*)(bb)     = *(const float4*)(bias + n);
            *(float4*)(bb + 4) = *(const float4*)(bias + n + 4);
            float out[8];
            #pragma unroll
            for (int t = 0; t < 8; t++) out[t] = stage[r * 16 + c0 + t] + bb[t];
            if (do_rope) {
                int l = m % L;           // token index
                int d0 = n & 63;         // dim within head (multiple of 8)
                #pragma unroll
                for (int t = 0; t < 8; t += 2) {
                    int pair = (d0 + t) >> 1;      // 0..31
                    int f = pair & 15;
                    int hi = pair >> 4;            // 0: x-rope, 1: y-rope
                    float cc = g_rope[hi ? 2 : 0][l][f];
                    float ss = g_rope[hi ? 3 : 1][l][f];
                    float xv = out[t], yv = out[t + 1];
                    out[t]     = xv * cc - yv * ss;
                    out[t + 1] = xv * ss + yv * cc;
                }
            }
            store_row8(C + (size_t)m * N + n, out);
        }
    }
}

// ---------------- fused attention: QK^T + softmax + P@V, 256 threads --------
// One CTA per (64-query tile, n*NH+h). All 576 key scores live in smem.
// 8 warps: 4x2 layout over the 64x64 tiles (warp = 16 rows x 32 cols).
#define LDT 72        // halves; 144B row stride
#define FA_LDS 584    // floats per score row (584 % 32 == 8)
#define FA_SMEM (64 * FA_LDS * 4 + 2 * 64 * LDT * 2)   // 167936

__global__ __launch_bounds__(256) void attn_fused(
        const __half* __restrict__ q, const __half* __restrict__ k,
        const __half* __restrict__ v, __half* __restrict__ o) {
    extern __shared__ __align__(16) unsigned char fsm[];
    float*  sS  = reinterpret_cast<float*>(fsm);
    __half* sSh = reinterpret_cast<__half*>(fsm);           // half view of sS
    __half* sQ  = reinterpret_cast<__half*>(fsm + 64 * FA_LDS * 4);
    __half* sKV = sQ + 64 * LDT;

    int mt = blockIdx.x;          // query tile 0..8
    int nh = blockIdx.y;          // n*NH + h
    int n = nh / NH, h = nh % NH;
    const __half* qb = q + ((size_t)n * L * NH + h) * HD;   // row stride 768
    const __half* kb = k + ((size_t)n * L * NH + h) * HD;
    const __half* vb = v + ((size_t)n * L * NH + h) * HD;
    __half* ob = o + ((size_t)n * L * NH + h) * HD;

    int tid = threadIdx.x;        // 256
    int wid = tid >> 5, lane = tid & 31;
    int wm = wid >> 1, wn = wid & 1;    // 4x2 warp layout: 16-row x 32-col per warp

    // ---- load Q tile: 64 rows x 64 halves = 512 float4, 2 per thread ----
    #pragma unroll
    for (int i = 0; i < 2; i++) {
        int idx = tid + i * 256;
        int row = idx >> 3, c8 = (idx & 7) * 8;
        *(float4*)&sQ[row * LDT + c8] =
            *(const float4*)(qb + (size_t)(mt * 64 + row) * (NH * HD) + c8);
    }

    // ---- phase 1: S = Q K^T for all 9 key tiles ----
    for (int kt = 0; kt < L / 64; kt++) {
        __syncthreads();   // protect sKV reuse (and Q store on first iter)
        #pragma unroll
        for (int i = 0; i < 2; i++) {
            int idx = tid + i * 256;
            int row = idx >> 3, c8 = (idx & 7) * 8;
            *(float4*)&sKV[row * LDT + c8] =
                *(const float4*)(kb + (size_t)(kt * 64 + row) * (NH * HD) + c8);
        }
        __syncthreads();
        wmma::fragment<wmma::accumulator, 16, 16, 16, float> acc[2];
        #pragma unroll
        for (int j = 0; j < 2; j++) wmma::fill_fragment(acc[j], 0.0f);
        #pragma unroll
        for (int k0 = 0; k0 < HD; k0 += 16) {
            wmma::fragment<wmma::matrix_a, 16, 16, 16, __half, wmma::row_major> af;
            wmma::fragment<wmma::matrix_b, 16, 16, 16, __half, wmma::col_major> bf[2];
            wmma::load_matrix_sync(af, &sQ[(wm * 16) * LDT + k0], LDT);
            #pragma unroll
            for (int j = 0; j < 2; j++)
                wmma::load_matrix_sync(bf[j], &sKV[(wn * 32 + j * 16) * LDT + k0], LDT);
            #pragma unroll
            for (int j = 0; j < 2; j++)
                wmma::mma_sync(acc[j], af, bf[j], acc[j]);
        }
        #pragma unroll
        for (int j = 0; j < 2; j++)
            wmma::store_matrix_sync(&sS[(wm * 16) * FA_LDS + kt * 64 + wn * 32 + j * 16],
                                    acc[j], FA_LDS, wmma::mem_row_major);
    }
    __syncthreads();   // all S tiles written

    // ---- phase 2: softmax per row (warp w owns rows 8w..8w+7) ----
    for (int rr = 0; rr < 8; rr++) {
        int row = wid * 8 + rr;
        float* rowp = sS + (size_t)row * FA_LDS;
        float r[18];
        float m = -1e30f;
        #pragma unroll
        for (int i = 0; i < 18; i++) { r[i] = rowp[lane + 32 * i]; m = fmaxf(m, r[i]); }
        #pragma unroll
        for (int off = 16; off > 0; off >>= 1) m = fmaxf(m, __shfl_xor_sync(0xffffffffu, m, off));
        float s = 0.f;
        #pragma unroll
        for (int i = 0; i < 18; i++) { r[i] = __expf(0.125f * (r[i] - m)); s += r[i]; }
        #pragma unroll
        for (int off = 16; off > 0; off >>= 1) s += __shfl_xor_sync(0xffffffffu, s, off);
        float inv = 1.0f / s;
        __syncwarp();   // all lanes done reading fp32 row before fp16 overwrite
        __half* rowh = sSh + (size_t)row * (2 * FA_LDS);
        #pragma unroll
        for (int i = 0; i < 18; i++) rowh[lane + 32 * i] = __float2half_rn(r[i] * inv);
    }
    __syncthreads();   // probs visible to all warps

    // ---- phase 3: O = P V, accumulate over 9 value tiles ----
    wmma::fragment<wmma::accumulator, 16, 16, 16, float> oacc[2];
    #pragma unroll
    for (int j = 0; j < 2; j++) wmma::fill_fragment(oacc[j], 0.0f);

    for (int kt = 0; kt < L / 64; kt++) {
        #pragma unroll
        for (int i = 0; i < 2; i++) {
            int idx = tid + i * 256;
            int row = idx >> 3, c8 = (idx & 7) * 8;
            *(float4*)&sKV[row * LDT + c8] =
                *(const float4*)(vb + (size_t)(kt * 64 + row) * (NH * HD) + c8);
        }
        __syncthreads();
        #pragma unroll
        for (int k0 = 0; k0 < 64; k0 += 16) {
            wmma::fragment<wmma::matrix_a, 16, 16, 16, __half, wmma::row_major> af;
            wmma::fragment<wmma::matrix_b, 16, 16, 16, __half, wmma::row_major> bf[2];
            wmma::load_matrix_sync(af,
                &sSh[(size_t)(wm * 16) * (2 * FA_LDS) + kt * 64 + k0], 2 * FA_LDS);
            #pragma unroll
            for (int j = 0; j < 2; j++)
                wmma::load_matrix_sync(bf[j], &sKV[k0 * LDT + wn * 32 + j * 16], LDT);
            #pragma unroll
            for (int j = 0; j < 2; j++)
                wmma::mma_sync(oacc[j], af, bf[j], oacc[j]);
        }
        __syncthreads();   // V tile consumed before next overwrite
    }

    // ---- epilogue: stage fp32 accum in sQ (free now), emit fp16 O ----
    float* stage = reinterpret_cast<float*>(sQ) + wid * 272;
    int r = lane >> 1, c0 = (lane & 1) * 8;
    #pragma unroll
    for (int j = 0; j < 2; j++) {
        __syncwarp();
        wmma::store_matrix_sync(stage, oacc[j], 16, wmma::mem_row_major);
        __syncwarp();
        float out[8];
        #pragma unroll
        for (int t = 0; t < 8; t++) out[t] = stage[r * 16 + c0 + t];
        store_row8(ob + (size_t)(mt * 64 + wm * 16 + r) * (NH * HD) + wn * 32 + j * 16 + c0, out);
    }
}

// ---------------- final mean over tokens ----------------
__global__ void mean_kernel(const float* __restrict__ y, float* __restrict__ out) {
    int n = blockIdx.x;
    int c = threadIdx.x;   // 768
    float s = 0.f;
    for (int l = 0; l < L; l++) s += y[((size_t)n * L + l) * W + c];
    out[n * W + c] = s * (1.0f / (float)L);
}

// ---------------- host orchestration ----------------
extern "C" void kernel_launch(void* const* d_in, const int* in_sizes, int n_in,
                              void* d_out, int out_size) {
    const float* image   = (const float*)d_in[0];
    const float* ckern   = (const float*)d_in[1];
    const float* cbias   = (const float*)d_in[2];
    const float* ln1s    = (const float*)d_in[3];
    const float* ln1b    = (const float*)d_in[4];
    const float* wq      = (const float*)d_in[5];
    const float* bq      = (const float*)d_in[6];
    const float* wk      = (const float*)d_in[7];
    const float* bk      = (const float*)d_in[8];
    const float* wv      = (const float*)d_in[9];
    const float* bv      = (const float*)d_in[10];
    const float* wo      = (const float*)d_in[11];
    const float* bo      = (const float*)d_in[12];
    const float* ln2s    = (const float*)d_in[13];
    const float* ln2b    = (const float*)d_in[14];
    const float* w1      = (const float*)d_in[15];
    const float* b1      = (const float*)d_in[16];
    const float* w2      = (const float*)d_in[17];
    const float* b2      = (const float*)d_in[18];
    const float* lnfs    = (const float*)d_in[19];
    const float* lnfb    = (const float*)d_in[20];
    float* out = (float*)d_out;

    float *x, *yf;
    __half *y, *q, *k, *v, *o, *hbuf, *wt;
    cudaGetSymbolAddress((void**)&x, g_x);
    cudaGetSymbolAddress((void**)&yf, g_yf);
    cudaGetSymbolAddress((void**)&y, g_y);
    cudaGetSymbolAddress((void**)&q, g_q);
    cudaGetSymbolAddress((void**)&k, g_k);
    cudaGetSymbolAddress((void**)&v, g_v);
    cudaGetSymbolAddress((void**)&o, g_o);
    cudaGetSymbolAddress((void**)&hbuf, g_h);
    cudaGetSymbolAddress((void**)&wt, g_wt);

    cudaFuncSetAttribute(attn_fused, cudaFuncAttributeMaxDynamicSharedMemorySize, FA_SMEM);

    const size_t WW = (size_t)W * W;       // == CONV_SZ
    const size_t WM = (size_t)W * MLP;

    // fp16 weight pool layout
    __half* convh = wt;                                  // [0, CONV)
    __half* wqh   = wt + (size_t)CONV_SZ;                // 4 layers
    __half* wkh   = wt + (size_t)CONV_SZ * 5;
    __half* wvh   = wt + (size_t)CONV_SZ * 9;
    __half* woh   = wt + (size_t)CONV_SZ * 13;
    __half* w1h   = wt + (size_t)CONV_SZ * 17;
    __half* w2h   = wt + (size_t)CONV_SZ * 17 + 4 * WM;

    CJobs jobs;
    jobs.j[0] = { ckern, convh, CONV_SZ / 4 };
    jobs.j[1] = { wq, wqh, (int)(4 * WW / 4) };
    jobs.j[2] = { wk, wkh, (int)(4 * WW / 4) };
    jobs.j[3] = { wv, wvh, (int)(4 * WW / 4) };
    jobs.j[4] = { wo, woh, (int)(4 * WW / 4) };
    jobs.j[5] = { w1, w1h, (int)(4 * WM / 4) };
    jobs.j[6] = { w2, w2h, (int)(4 * WM / 4) };
    cvt_weights<<<dim3(1024, 7), 256>>>(jobs);

    // patch embed: im2col + GEMM
    {
        int total = M_ROWS * W;
        im2col_kernel<<<(total + 255) / 256, 256>>>(image, y);
        dim3 gg(W / GBN, M_ROWS / GBM);
        gemm_tc<0, float><<<gg, 256>>>(y, convh, cbias, nullptr, x, M_ROWS, W, W);
    }
    rope_cache_kernel<<<(L * 16 + 255) / 256, 256>>>();

    dim3 gw(W / GBN, M_ROWS / GBM);        // 768-wide GEMMs: (6, 36)
    dim3 gqkv(W / GBN, M_ROWS / GBM, 3);   // fused QKV: (6, 36, 3)
    dim3 gm(MLP / GBN, M_ROWS / GBM);      // 3072-wide GEMM: (24, 36)
    dim3 gat(L / 64, NB * NH);             // fused attention: (9, 96)

    for (int l = 0; l < DPT; l++) {
        ln_warp<__half><<<M_ROWS / 8, 256>>>(x, ln1s + l * W, ln1b + l * W, y);
        gemm_qkv<<<gqkv, 256>>>(y, wqh + l * WW, wkh + l * WW, wvh + l * WW,
                                bq + l * W, bk + l * W, bv + l * W,
                                q, k, v, M_ROWS, W, W);
        attn_fused<<<gat, 256, FA_SMEM>>>(q, k, v, o);
        // x = x + (o @ wo + bo)
        gemm_tc<2, float><<<gw, 256>>>(o, woh + l * WW, bo + l * W, x, x, M_ROWS, W, W);
        ln_warp<__half><<<M_ROWS / 8, 256>>>(x, ln2s + l * W, ln2b + l * W, y);
        gemm_tc<1, __half><<<gm, 256>>>(y, w1h + l * WM, b1 + l * MLP, nullptr, hbuf, M_ROWS, MLP, W);
        gemm_tc<2, float><<<gw, 256>>>(hbuf, w2h + l * WM, b2 + l * W, x, x, M_ROWS, W, MLP);
    }

    ln_warp<float><<<M_ROWS / 8, 256>>>(x, lnfs, lnfb, yf);
    mean_kernel<<<NB, W>>>(yf, out);
}